// round 7
// baseline (speedup 1.0000x reference)
#include <cuda_runtime.h>
#include <cuda_bf16.h>
#include <stdint.h>

#define NNODES 100000
#define FDIM   64
#define EMAX   2000000   // reference uses E=1.6M; headroom

#define SCAN_BLK   1024
#define NSCANBLK   ((NNODES + SCAN_BLK - 1) / SCAN_BLK)   // 98

#define ROWS_PER_BLK 256
#define A_STRIDE4    17          // float4 stride per smem row (68 floats)

// ---------------------------------------------------------------------------
// Static device scratch (no allocation allowed anywhere)
// ---------------------------------------------------------------------------
__device__ __align__(16) float g_h[(size_t)NNODES * FDIM];    // 25.6 MB
__device__ float g_dinv[NNODES];
__device__ int   g_degi[NNODES];
__device__ int   g_off[NNODES + 1];
__device__ int   g_cursor[NNODES];
__device__ int   g_bsum[NSCANBLK];
__device__ int   g_bpre[NSCANBLK];
__device__ __align__(8) int2 g_csr[EMAX];   // {src, bitcast(dinv[src])} 16 MB

// ---------------------------------------------------------------------------
__global__ void zero_deg_kernel() {
    int i = blockIdx.x * blockDim.x + threadIdx.x;
    if (i < NNODES) g_degi[i] = 0;
}

// histogram of in-edges (int atomics, exact)
__global__ void hist_kernel(const int* __restrict__ ei, long long E) {
    long long stride = (long long)gridDim.x * blockDim.x;
    for (long long e = (long long)blockIdx.x * blockDim.x + threadIdx.x;
         e < E; e += stride)
        atomicAdd(&g_degi[ei[E + e]], 1);
}

__global__ void dinv_kernel() {
    int i = blockIdx.x * blockDim.x + threadIdx.x;
    if (i < NNODES) g_dinv[i] = rsqrtf((float)g_degi[i] + 1.0f);
}

// ---------------------------------------------------------------------------
// Multi-block exclusive scan of g_degi -> g_off (+ cursor copy). 3 phases.
// ---------------------------------------------------------------------------
__global__ __launch_bounds__(SCAN_BLK) void scan_reduce_kernel() {
    __shared__ int sh[SCAN_BLK / 32];
    int i = blockIdx.x * SCAN_BLK + threadIdx.x;
    int v = (i < NNODES) ? g_degi[i] : 0;
#pragma unroll
    for (int o = 16; o > 0; o >>= 1)
        v += __shfl_down_sync(0xffffffffu, v, o);
    if ((threadIdx.x & 31) == 0) sh[threadIdx.x >> 5] = v;
    __syncthreads();
    if (threadIdx.x < 32) {
        int w = (threadIdx.x < SCAN_BLK / 32) ? sh[threadIdx.x] : 0;
#pragma unroll
        for (int o = 16; o > 0; o >>= 1)
            w += __shfl_down_sync(0xffffffffu, w, o);
        if (threadIdx.x == 0) g_bsum[blockIdx.x] = w;
    }
}

__global__ __launch_bounds__(128) void scan_bsum_kernel() {
    __shared__ int sh[128];
    int tid = threadIdx.x;
    int v = (tid < NSCANBLK) ? g_bsum[tid] : 0;
    sh[tid] = v;
    __syncthreads();
    for (int o = 1; o < 128; o <<= 1) {
        int t = (tid >= o) ? sh[tid - o] : 0;
        __syncthreads();
        sh[tid] += t;
        __syncthreads();
    }
    if (tid < NSCANBLK) g_bpre[tid] = sh[tid] - v;   // exclusive
    if (tid == 127) g_off[NNODES] = sh[127];         // total
}

__global__ __launch_bounds__(SCAN_BLK) void scan_write_kernel() {
    __shared__ int sh[SCAN_BLK];
    int tid = threadIdx.x;
    int i = blockIdx.x * SCAN_BLK + tid;
    int v = (i < NNODES) ? g_degi[i] : 0;
    sh[tid] = v;
    __syncthreads();
    for (int o = 1; o < SCAN_BLK; o <<= 1) {
        int t = (tid >= o) ? sh[tid - o] : 0;
        __syncthreads();
        sh[tid] += t;
        __syncthreads();
    }
    if (i < NNODES) {
        int off = g_bpre[blockIdx.x] + sh[tid] - v;  // exclusive
        g_off[i]    = off;
        g_cursor[i] = off;
    }
}

// ---------------------------------------------------------------------------
// CSR fill: csr[pos] = {src, dinv[src]}  (packed 8B write per edge)
// ---------------------------------------------------------------------------
__global__ void fill_kernel(const int* __restrict__ ei, long long E) {
    long long stride = (long long)gridDim.x * blockDim.x;
    for (long long e = (long long)blockIdx.x * blockDim.x + threadIdx.x;
         e < E; e += stride) {
        int s = ei[e];
        int d = ei[E + e];
        int pos = atomicAdd(&g_cursor[d], 1);
        g_csr[pos] = make_int2(s, __float_as_int(g_dinv[s]));
    }
}

// ---------------------------------------------------------------------------
// FUSED layer: C[node] = relu( (Â x)[node] @ W + b )
// Block = 256 threads / 256 nodes.
// Phase 1: 8 warps aggregate 32 nodes each (CSR gather) -> smem tile.
// Phase 2: block GEMM from smem (4 rows x 16 cols per thread) + bias + ReLU.
// ---------------------------------------------------------------------------
__global__ __launch_bounds__(256, 2) void fused_layer_kernel(
    const float* __restrict__ x, const float* __restrict__ W,
    const float* __restrict__ bias, float* __restrict__ C)
{
    extern __shared__ float smem[];
    float*  sW  = smem;                                        // 4096 floats
    float4* sA4 = reinterpret_cast<float4*>(smem + 64 * 64);   // 256*17 float4

    const int tid  = threadIdx.x;
    const int lane = tid & 31;
    const int warp = tid >> 5;
    const int row0 = blockIdx.x * ROWS_PER_BLK;

    // Load W while gathers are in flight later (issue first, cheap)
    for (int i = tid; i < 1024; i += 256)
        reinterpret_cast<float4*>(sW)[i] =
            reinterpret_cast<const float4*>(W)[i];

    // ---- Phase 1: aggregate 32 nodes per warp into smem tile ----
    for (int i = 0; i < 32; i++) {
        const int rloc = warp * 32 + i;
        const int node = row0 + rloc;

        float2 acc = make_float2(0.f, 0.f);
        if (node < NNODES) {
            const int beg = g_off[node];
            const int end = g_off[node + 1];

            for (int base = beg; base < end; base += 32) {
                const int cnt = min(32, end - base);
                int   s = 0;
                float w = 0.f;
                if (lane < cnt) {
                    int2 ent = g_csr[base + lane];
                    s = ent.x;
                    w = __int_as_float(ent.y);
                }
#pragma unroll 4
                for (int j = 0; j < cnt; j++) {
                    int   sj = __shfl_sync(0xffffffffu, s, j);
                    float wj = __shfl_sync(0xffffffffu, w, j);
                    float2 v = *reinterpret_cast<const float2*>(
                        x + (size_t)sj * FDIM + lane * 2);
                    acc.x = fmaf(wj, v.x, acc.x);
                    acc.y = fmaf(wj, v.y, acc.y);
                }
            }

            const float di = g_dinv[node];
            float2 sv = *reinterpret_cast<const float2*>(
                x + (size_t)node * FDIM + lane * 2);
            acc.x = fmaf(di, sv.x, acc.x) * di;
            acc.y = fmaf(di, sv.y, acc.y) * di;
        }
        float* dst = reinterpret_cast<float*>(&sA4[rloc * A_STRIDE4]) + lane * 2;
        dst[0] = acc.x;
        dst[1] = acc.y;
    }
    __syncthreads();

    // ---- Phase 2: GEMM from smem tile ----
    const int rbase = (tid >> 2) * 4;
    const int cg    = (tid & 3) * 16;

    float acc[4][16];
#pragma unroll
    for (int r = 0; r < 4; r++)
#pragma unroll
        for (int i = 0; i < 16; i++) acc[r][i] = 0.f;

#pragma unroll
    for (int k4 = 0; k4 < 16; k4++) {
        float4 a[4];
#pragma unroll
        for (int r = 0; r < 4; r++)
            a[r] = sA4[(rbase + r) * A_STRIDE4 + k4];

#pragma unroll
        for (int kk = 0; kk < 4; kk++) {
            const float4* wr = reinterpret_cast<const float4*>(
                sW + (k4 * 4 + kk) * 64 + cg);
            float4 w0 = wr[0], w1 = wr[1], w2 = wr[2], w3 = wr[3];
#pragma unroll
            for (int r = 0; r < 4; r++) {
                float av = (&a[r].x)[kk];
                acc[r][0]  = fmaf(av, w0.x, acc[r][0]);
                acc[r][1]  = fmaf(av, w0.y, acc[r][1]);
                acc[r][2]  = fmaf(av, w0.z, acc[r][2]);
                acc[r][3]  = fmaf(av, w0.w, acc[r][3]);
                acc[r][4]  = fmaf(av, w1.x, acc[r][4]);
                acc[r][5]  = fmaf(av, w1.y, acc[r][5]);
                acc[r][6]  = fmaf(av, w1.z, acc[r][6]);
                acc[r][7]  = fmaf(av, w1.w, acc[r][7]);
                acc[r][8]  = fmaf(av, w2.x, acc[r][8]);
                acc[r][9]  = fmaf(av, w2.y, acc[r][9]);
                acc[r][10] = fmaf(av, w2.z, acc[r][10]);
                acc[r][11] = fmaf(av, w2.w, acc[r][11]);
                acc[r][12] = fmaf(av, w3.x, acc[r][12]);
                acc[r][13] = fmaf(av, w3.y, acc[r][13]);
                acc[r][14] = fmaf(av, w3.z, acc[r][14]);
                acc[r][15] = fmaf(av, w3.w, acc[r][15]);
            }
        }
    }

    float4 bv[4];
#pragma unroll
    for (int i = 0; i < 4; i++)
        bv[i] = reinterpret_cast<const float4*>(bias + cg)[i];

#pragma unroll
    for (int r = 0; r < 4; r++) {
        int row = row0 + rbase + r;
        if (row < NNODES) {
            float4* o = reinterpret_cast<float4*>(C + (size_t)row * FDIM + cg);
#pragma unroll
            for (int i = 0; i < 4; i++)
                o[i] = make_float4(
                    fmaxf(acc[r][4*i+0] + bv[i].x, 0.f),
                    fmaxf(acc[r][4*i+1] + bv[i].y, 0.f),
                    fmaxf(acc[r][4*i+2] + bv[i].z, 0.f),
                    fmaxf(acc[r][4*i+3] + bv[i].w, 0.f));
        }
    }
}

// ---------------------------------------------------------------------------
extern "C" void kernel_launch(void* const* d_in, const int* in_sizes, int n_in,
                              void* d_out, int out_size)
{
    const float* x  = (const float*)d_in[0];
    const int*   ei = (const int*)d_in[1];     // int32 (JAX x64 disabled)
    const float* W1 = (const float*)d_in[2];
    const float* b1 = (const float*)d_in[3];
    const float* W2 = (const float*)d_in[4];
    const float* b2 = (const float*)d_in[5];
    float* out = (float*)d_out;

    const long long E = (long long)in_sizes[1] / 2;

    float* g_h_ptr; cudaGetSymbolAddress((void**)&g_h_ptr, g_h);

    const int SMS = 148;
    dim3 blk(256);

    const int FUSED_SMEM = (64 * 64 + ROWS_PER_BLK * A_STRIDE4 * 4) * 4; // 84 KB
    static bool attr_done = false;
    if (!attr_done) {
        cudaFuncSetAttribute(fused_layer_kernel,
            cudaFuncAttributeMaxDynamicSharedMemorySize, FUSED_SMEM);
        attr_done = true;
    }

    // ---- CSR build (once per launch, reused by both layers) ----
    zero_deg_kernel<<<(NNODES + 255) / 256, blk>>>();
    hist_kernel<<<SMS * 8, blk>>>(ei, E);
    dinv_kernel<<<(NNODES + 255) / 256, blk>>>();
    scan_reduce_kernel<<<NSCANBLK, SCAN_BLK>>>();
    scan_bsum_kernel<<<1, 128>>>();
    scan_write_kernel<<<NSCANBLK, SCAN_BLK>>>();
    fill_kernel<<<SMS * 8, blk>>>(ei, E);

    const int grid = (NNODES + ROWS_PER_BLK - 1) / ROWS_PER_BLK;  // 391

    // ---- layer 1:  h1 = relu((Â x) W1 + b1) ----
    fused_layer_kernel<<<grid, blk, FUSED_SMEM>>>(x, W1, b1, g_h_ptr);

    // ---- layer 2:  out = relu((Â h1) W2 + b2) ----
    fused_layer_kernel<<<grid, blk, FUSED_SMEM>>>(g_h_ptr, W2, b2, out);
}

// round 8
// speedup vs baseline: 1.8156x; 1.8156x over previous
#include <cuda_runtime.h>
#include <cuda_bf16.h>
#include <stdint.h>

#define NNODES 100000
#define FDIM   64
#define EMAX   2000000   // reference uses E=1.6M; headroom

#define SCAN_BLK   1024
#define NSCANBLK   ((NNODES + SCAN_BLK - 1) / SCAN_BLK)   // 98

// ---------------------------------------------------------------------------
// Static device scratch (no allocation allowed anywhere)
// ---------------------------------------------------------------------------
__device__ __align__(16) float g_h[(size_t)NNODES * FDIM];    // 25.6 MB
__device__ __align__(16) float g_agg[(size_t)NNODES * FDIM];  // 25.6 MB
__device__ float g_dinv[NNODES];
__device__ int   g_degi[NNODES];
__device__ int   g_off[NNODES + 1];
__device__ int   g_cursor[NNODES];
__device__ int   g_bsum[NSCANBLK];
__device__ int   g_bpre[NSCANBLK];
__device__ __align__(8) int2 g_csr[EMAX];   // {src, bitcast(dinv[src])} 16 MB

// ---------------------------------------------------------------------------
__global__ void zero_deg_kernel() {
    int i = blockIdx.x * blockDim.x + threadIdx.x;
    if (i < NNODES) g_degi[i] = 0;
}

// histogram of in-edges (int atomics, exact)
__global__ void hist_kernel(const int* __restrict__ ei, long long E) {
    long long stride = (long long)gridDim.x * blockDim.x;
    for (long long e = (long long)blockIdx.x * blockDim.x + threadIdx.x;
         e < E; e += stride)
        atomicAdd(&g_degi[ei[E + e]], 1);
}

__global__ void dinv_kernel() {
    int i = blockIdx.x * blockDim.x + threadIdx.x;
    if (i < NNODES) g_dinv[i] = rsqrtf((float)g_degi[i] + 1.0f);
}

// ---------------------------------------------------------------------------
// Multi-block exclusive scan of g_degi -> g_off (+ cursor copy). 3 phases.
// ---------------------------------------------------------------------------
__global__ __launch_bounds__(SCAN_BLK) void scan_reduce_kernel() {
    __shared__ int sh[SCAN_BLK / 32];
    int i = blockIdx.x * SCAN_BLK + threadIdx.x;
    int v = (i < NNODES) ? g_degi[i] : 0;
#pragma unroll
    for (int o = 16; o > 0; o >>= 1)
        v += __shfl_down_sync(0xffffffffu, v, o);
    if ((threadIdx.x & 31) == 0) sh[threadIdx.x >> 5] = v;
    __syncthreads();
    if (threadIdx.x < 32) {
        int w = (threadIdx.x < SCAN_BLK / 32) ? sh[threadIdx.x] : 0;
#pragma unroll
        for (int o = 16; o > 0; o >>= 1)
            w += __shfl_down_sync(0xffffffffu, w, o);
        if (threadIdx.x == 0) g_bsum[blockIdx.x] = w;
    }
}

__global__ __launch_bounds__(128) void scan_bsum_kernel() {
    __shared__ int sh[128];
    int tid = threadIdx.x;
    int v = (tid < NSCANBLK) ? g_bsum[tid] : 0;
    sh[tid] = v;
    __syncthreads();
    for (int o = 1; o < 128; o <<= 1) {
        int t = (tid >= o) ? sh[tid - o] : 0;
        __syncthreads();
        sh[tid] += t;
        __syncthreads();
    }
    if (tid < NSCANBLK) g_bpre[tid] = sh[tid] - v;   // exclusive
    if (tid == 127) g_off[NNODES] = sh[127];         // total
}

__global__ __launch_bounds__(SCAN_BLK) void scan_write_kernel() {
    __shared__ int sh[SCAN_BLK];
    int tid = threadIdx.x;
    int i = blockIdx.x * SCAN_BLK + tid;
    int v = (i < NNODES) ? g_degi[i] : 0;
    sh[tid] = v;
    __syncthreads();
    for (int o = 1; o < SCAN_BLK; o <<= 1) {
        int t = (tid >= o) ? sh[tid - o] : 0;
        __syncthreads();
        sh[tid] += t;
        __syncthreads();
    }
    if (i < NNODES) {
        int off = g_bpre[blockIdx.x] + sh[tid] - v;  // exclusive
        g_off[i]    = off;
        g_cursor[i] = off;
    }
}

// ---------------------------------------------------------------------------
// CSR fill: csr[pos] = {src, dinv[src]}  (packed 8B write per edge)
// ---------------------------------------------------------------------------
__global__ void fill_kernel(const int* __restrict__ ei, long long E) {
    long long stride = (long long)gridDim.x * blockDim.x;
    for (long long e = (long long)blockIdx.x * blockDim.x + threadIdx.x;
         e < E; e += stride) {
        int s = ei[e];
        int d = ei[E + e];
        int pos = atomicAdd(&g_cursor[d], 1);
        g_csr[pos] = make_int2(s, __float_as_int(g_dinv[s]));
    }
}

// ---------------------------------------------------------------------------
// Aggregation (gather form): out[node] = dinv[node]*(sum_e dinv[src] x[src]
//                                          + dinv[node]*x[node])
// One warp per node; each lane owns 2 of the 64 features (float2).
// 4 independent accumulator pairs break the FMA RAW chain and keep 4
// independent gather loads in flight per step.
// ---------------------------------------------------------------------------
__global__ __launch_bounds__(256) void agg_kernel(
    const float* __restrict__ x, float* __restrict__ outv)
{
    const int lane = threadIdx.x & 31;
    const int gwarp = (blockIdx.x * blockDim.x + threadIdx.x) >> 5;
    const int nwarp = (gridDim.x * blockDim.x) >> 5;

    for (int node = gwarp; node < NNODES; node += nwarp) {
        const int beg = g_off[node];
        const int end = g_off[node + 1];

        float2 a0 = make_float2(0.f, 0.f);
        float2 a1 = make_float2(0.f, 0.f);
        float2 a2 = make_float2(0.f, 0.f);
        float2 a3 = make_float2(0.f, 0.f);

        for (int base = beg; base < end; base += 32) {
            const int cnt = min(32, end - base);
            int   s = 0;
            float w = 0.f;
            if (lane < cnt) {
                int2 ent = g_csr[base + lane];
                s = ent.x;
                w = __int_as_float(ent.y);
            }

            int j = 0;
            for (; j + 4 <= cnt; j += 4) {
                int   s0 = __shfl_sync(0xffffffffu, s, j + 0);
                int   s1 = __shfl_sync(0xffffffffu, s, j + 1);
                int   s2 = __shfl_sync(0xffffffffu, s, j + 2);
                int   s3 = __shfl_sync(0xffffffffu, s, j + 3);
                float w0 = __shfl_sync(0xffffffffu, w, j + 0);
                float w1 = __shfl_sync(0xffffffffu, w, j + 1);
                float w2 = __shfl_sync(0xffffffffu, w, j + 2);
                float w3 = __shfl_sync(0xffffffffu, w, j + 3);
                float2 v0 = *reinterpret_cast<const float2*>(
                    x + (size_t)s0 * FDIM + lane * 2);
                float2 v1 = *reinterpret_cast<const float2*>(
                    x + (size_t)s1 * FDIM + lane * 2);
                float2 v2 = *reinterpret_cast<const float2*>(
                    x + (size_t)s2 * FDIM + lane * 2);
                float2 v3 = *reinterpret_cast<const float2*>(
                    x + (size_t)s3 * FDIM + lane * 2);
                a0.x = fmaf(w0, v0.x, a0.x);  a0.y = fmaf(w0, v0.y, a0.y);
                a1.x = fmaf(w1, v1.x, a1.x);  a1.y = fmaf(w1, v1.y, a1.y);
                a2.x = fmaf(w2, v2.x, a2.x);  a2.y = fmaf(w2, v2.y, a2.y);
                a3.x = fmaf(w3, v3.x, a3.x);  a3.y = fmaf(w3, v3.y, a3.y);
            }
            for (; j < cnt; j++) {
                int   sj = __shfl_sync(0xffffffffu, s, j);
                float wj = __shfl_sync(0xffffffffu, w, j);
                float2 v = *reinterpret_cast<const float2*>(
                    x + (size_t)sj * FDIM + lane * 2);
                a0.x = fmaf(wj, v.x, a0.x);
                a0.y = fmaf(wj, v.y, a0.y);
            }
        }

        float2 acc;
        acc.x = (a0.x + a1.x) + (a2.x + a3.x);
        acc.y = (a0.y + a1.y) + (a2.y + a3.y);

        const float di = g_dinv[node];
        float2 sv = *reinterpret_cast<const float2*>(
            x + (size_t)node * FDIM + lane * 2);
        acc.x = fmaf(di, sv.x, acc.x) * di;
        acc.y = fmaf(di, sv.y, acc.y) * di;
        *reinterpret_cast<float2*>(outv + (size_t)node * FDIM + lane * 2) = acc;
    }
}

// ---------------------------------------------------------------------------
// GEMM: C[n,64] = relu(A[n,64] @ W[64,64] + b), fp32.
// 256 threads / 256 rows per block; 4 rows x 16 cols per thread.
// ---------------------------------------------------------------------------
#define ROWS_PER_BLK 256
#define A_STRIDE4    17

__global__ __launch_bounds__(256) void gemm64_kernel(
    const float* __restrict__ A, const float* __restrict__ W,
    const float* __restrict__ bias, float* __restrict__ C, int n_rows)
{
    extern __shared__ float smem[];
    float*  sW  = smem;                                        // 4096 floats
    float4* sA4 = reinterpret_cast<float4*>(smem + 64 * 64);   // 256*17 float4

    const int tid  = threadIdx.x;
    const int row0 = blockIdx.x * ROWS_PER_BLK;

    for (int i = tid; i < 1024; i += 256)
        reinterpret_cast<float4*>(sW)[i] =
            reinterpret_cast<const float4*>(W)[i];

    for (int i = tid; i < ROWS_PER_BLK * 16; i += 256) {
        int r  = i >> 4;
        int c4 = i & 15;
        int row = row0 + r;
        float4 v = make_float4(0.f, 0.f, 0.f, 0.f);
        if (row < n_rows)
            v = reinterpret_cast<const float4*>(A + (size_t)row * FDIM)[c4];
        sA4[r * A_STRIDE4 + c4] = v;
    }
    __syncthreads();

    const int rbase = (tid >> 2) * 4;
    const int cg    = (tid & 3) * 16;

    float acc[4][16];
#pragma unroll
    for (int r = 0; r < 4; r++)
#pragma unroll
        for (int i = 0; i < 16; i++) acc[r][i] = 0.f;

#pragma unroll
    for (int k4 = 0; k4 < 16; k4++) {
        float4 a[4];
#pragma unroll
        for (int r = 0; r < 4; r++)
            a[r] = sA4[(rbase + r) * A_STRIDE4 + k4];

#pragma unroll
        for (int kk = 0; kk < 4; kk++) {
            const float4* wr = reinterpret_cast<const float4*>(
                sW + (k4 * 4 + kk) * 64 + cg);
            float4 w0 = wr[0], w1 = wr[1], w2 = wr[2], w3 = wr[3];
#pragma unroll
            for (int r = 0; r < 4; r++) {
                float av = (&a[r].x)[kk];
                acc[r][0]  = fmaf(av, w0.x, acc[r][0]);
                acc[r][1]  = fmaf(av, w0.y, acc[r][1]);
                acc[r][2]  = fmaf(av, w0.z, acc[r][2]);
                acc[r][3]  = fmaf(av, w0.w, acc[r][3]);
                acc[r][4]  = fmaf(av, w1.x, acc[r][4]);
                acc[r][5]  = fmaf(av, w1.y, acc[r][5]);
                acc[r][6]  = fmaf(av, w1.z, acc[r][6]);
                acc[r][7]  = fmaf(av, w1.w, acc[r][7]);
                acc[r][8]  = fmaf(av, w2.x, acc[r][8]);
                acc[r][9]  = fmaf(av, w2.y, acc[r][9]);
                acc[r][10] = fmaf(av, w2.z, acc[r][10]);
                acc[r][11] = fmaf(av, w2.w, acc[r][11]);
                acc[r][12] = fmaf(av, w3.x, acc[r][12]);
                acc[r][13] = fmaf(av, w3.y, acc[r][13]);
                acc[r][14] = fmaf(av, w3.z, acc[r][14]);
                acc[r][15] = fmaf(av, w3.w, acc[r][15]);
            }
        }
    }

    float4 bv[4];
#pragma unroll
    for (int i = 0; i < 4; i++)
        bv[i] = reinterpret_cast<const float4*>(bias + cg)[i];

#pragma unroll
    for (int r = 0; r < 4; r++) {
        int row = row0 + rbase + r;
        if (row < n_rows) {
            float4* o = reinterpret_cast<float4*>(C + (size_t)row * FDIM + cg);
#pragma unroll
            for (int i = 0; i < 4; i++)
                o[i] = make_float4(
                    fmaxf(acc[r][4*i+0] + bv[i].x, 0.f),
                    fmaxf(acc[r][4*i+1] + bv[i].y, 0.f),
                    fmaxf(acc[r][4*i+2] + bv[i].z, 0.f),
                    fmaxf(acc[r][4*i+3] + bv[i].w, 0.f));
        }
    }
}

// ---------------------------------------------------------------------------
extern "C" void kernel_launch(void* const* d_in, const int* in_sizes, int n_in,
                              void* d_out, int out_size)
{
    const float* x  = (const float*)d_in[0];
    const int*   ei = (const int*)d_in[1];     // int32 (JAX x64 disabled)
    const float* W1 = (const float*)d_in[2];
    const float* b1 = (const float*)d_in[3];
    const float* W2 = (const float*)d_in[4];
    const float* b2 = (const float*)d_in[5];
    float* out = (float*)d_out;

    const long long E = (long long)in_sizes[1] / 2;

    float* g_h_ptr;   cudaGetSymbolAddress((void**)&g_h_ptr,   g_h);
    float* g_agg_ptr; cudaGetSymbolAddress((void**)&g_agg_ptr, g_agg);

    const int SMS = 148;
    dim3 blk(256);

    const int GEMM_SMEM = (64 * 64 + ROWS_PER_BLK * A_STRIDE4 * 4) * 4; // 84 KB
    static bool attr_done = false;
    if (!attr_done) {
        cudaFuncSetAttribute(gemm64_kernel,
            cudaFuncAttributeMaxDynamicSharedMemorySize, GEMM_SMEM);
        attr_done = true;
    }

    // ---- CSR build (once per launch, reused by both layers) ----
    zero_deg_kernel<<<(NNODES + 255) / 256, blk>>>();
    hist_kernel<<<SMS * 8, blk>>>(ei, E);
    dinv_kernel<<<(NNODES + 255) / 256, blk>>>();
    scan_reduce_kernel<<<NSCANBLK, SCAN_BLK>>>();
    scan_bsum_kernel<<<1, 128>>>();
    scan_write_kernel<<<NSCANBLK, SCAN_BLK>>>();
    fill_kernel<<<SMS * 8, blk>>>(ei, E);

    const int gemm_grid = (NNODES + ROWS_PER_BLK - 1) / ROWS_PER_BLK;
    const int agg_grid  = SMS * 24;

    // ---- layer 1:  h1 = relu((Â x) W1 + b1) ----
    agg_kernel<<<agg_grid, blk>>>(x, g_agg_ptr);
    gemm64_kernel<<<gemm_grid, blk, GEMM_SMEM>>>(g_agg_ptr, W1, b1, g_h_ptr, NNODES);

    // ---- layer 2:  out = relu((Â h1) W2 + b2) ----
    agg_kernel<<<agg_grid, blk>>>(g_h_ptr, g_agg_ptr);
    gemm64_kernel<<<gemm_grid, blk, GEMM_SMEM>>>(g_agg_ptr, W2, b2, out, NNODES);
}

// round 9
// speedup vs baseline: 2.0086x; 1.1063x over previous
#include <cuda_runtime.h>
#include <cuda_bf16.h>
#include <stdint.h>

#define NNODES 100000
#define FDIM   64
#define EMAX   2000000   // reference uses E=1.6M; headroom

#define SCAN_BLK   1024
#define NSCANBLK   ((NNODES + SCAN_BLK - 1) / SCAN_BLK)   // 98

// ---------------------------------------------------------------------------
// Static device scratch (no allocation allowed anywhere)
// ---------------------------------------------------------------------------
__device__ __align__(16) float g_h[(size_t)NNODES * FDIM];    // 25.6 MB
__device__ __align__(16) float g_agg[(size_t)NNODES * FDIM];  // 25.6 MB
__device__ float g_dinv[NNODES];
__device__ int   g_degi[NNODES];
__device__ int   g_off[NNODES + 1];
__device__ int   g_cursor[NNODES];
__device__ int   g_bsum[NSCANBLK];
__device__ int   g_bpre[NSCANBLK];
__device__ __align__(8) int2 g_csr[EMAX];   // {src, bitcast(dinv[src])} 16 MB

// ---------------------------------------------------------------------------
__global__ void zero_deg_kernel() {
    int i = blockIdx.x * blockDim.x + threadIdx.x;
    if (i < NNODES) g_degi[i] = 0;
}

// histogram of in-edges (int atomics, exact)
__global__ void hist_kernel(const int* __restrict__ ei, long long E) {
    long long stride = (long long)gridDim.x * blockDim.x;
    for (long long e = (long long)blockIdx.x * blockDim.x + threadIdx.x;
         e < E; e += stride)
        atomicAdd(&g_degi[ei[E + e]], 1);
}

__global__ void dinv_kernel() {
    int i = blockIdx.x * blockDim.x + threadIdx.x;
    if (i < NNODES) g_dinv[i] = rsqrtf((float)g_degi[i] + 1.0f);
}

// ---------------------------------------------------------------------------
// Multi-block exclusive scan of g_degi -> g_off (+ cursor copy). 3 phases.
// ---------------------------------------------------------------------------
__global__ __launch_bounds__(SCAN_BLK) void scan_reduce_kernel() {
    __shared__ int sh[SCAN_BLK / 32];
    int i = blockIdx.x * SCAN_BLK + threadIdx.x;
    int v = (i < NNODES) ? g_degi[i] : 0;
#pragma unroll
    for (int o = 16; o > 0; o >>= 1)
        v += __shfl_down_sync(0xffffffffu, v, o);
    if ((threadIdx.x & 31) == 0) sh[threadIdx.x >> 5] = v;
    __syncthreads();
    if (threadIdx.x < 32) {
        int w = (threadIdx.x < SCAN_BLK / 32) ? sh[threadIdx.x] : 0;
#pragma unroll
        for (int o = 16; o > 0; o >>= 1)
            w += __shfl_down_sync(0xffffffffu, w, o);
        if (threadIdx.x == 0) g_bsum[blockIdx.x] = w;
    }
}

__global__ __launch_bounds__(128) void scan_bsum_kernel() {
    __shared__ int sh[128];
    int tid = threadIdx.x;
    int v = (tid < NSCANBLK) ? g_bsum[tid] : 0;
    sh[tid] = v;
    __syncthreads();
    for (int o = 1; o < 128; o <<= 1) {
        int t = (tid >= o) ? sh[tid - o] : 0;
        __syncthreads();
        sh[tid] += t;
        __syncthreads();
    }
    if (tid < NSCANBLK) g_bpre[tid] = sh[tid] - v;   // exclusive
    if (tid == 127) g_off[NNODES] = sh[127];         // total
}

__global__ __launch_bounds__(SCAN_BLK) void scan_write_kernel() {
    __shared__ int sh[SCAN_BLK];
    int tid = threadIdx.x;
    int i = blockIdx.x * SCAN_BLK + tid;
    int v = (i < NNODES) ? g_degi[i] : 0;
    sh[tid] = v;
    __syncthreads();
    for (int o = 1; o < SCAN_BLK; o <<= 1) {
        int t = (tid >= o) ? sh[tid - o] : 0;
        __syncthreads();
        sh[tid] += t;
        __syncthreads();
    }
    if (i < NNODES) {
        int off = g_bpre[blockIdx.x] + sh[tid] - v;  // exclusive
        g_off[i]    = off;
        g_cursor[i] = off;
    }
}

// ---------------------------------------------------------------------------
// CSR fill: csr[pos] = {src, dinv[src]}  (packed 8B write per edge)
// ---------------------------------------------------------------------------
__global__ void fill_kernel(const int* __restrict__ ei, long long E) {
    long long stride = (long long)gridDim.x * blockDim.x;
    for (long long e = (long long)blockIdx.x * blockDim.x + threadIdx.x;
         e < E; e += stride) {
        int s = ei[e];
        int d = ei[E + e];
        int pos = atomicAdd(&g_cursor[d], 1);
        g_csr[pos] = make_int2(s, __float_as_int(g_dinv[s]));
    }
}

// ---------------------------------------------------------------------------
// Aggregation (gather form): out[node] = dinv[node]*(sum_e dinv[src] x[src]
//                                          + dinv[node]*x[node])
// One warp per node; each lane owns 2 of the 64 features (float2).
// ---------------------------------------------------------------------------
__global__ __launch_bounds__(256) void agg_kernel(
    const float* __restrict__ x, float* __restrict__ outv)
{
    const int lane = threadIdx.x & 31;
    const int gwarp = (blockIdx.x * blockDim.x + threadIdx.x) >> 5;
    const int nwarp = (gridDim.x * blockDim.x) >> 5;

    for (int node = gwarp; node < NNODES; node += nwarp) {
        const int beg = g_off[node];
        const int end = g_off[node + 1];

        float2 a0 = make_float2(0.f, 0.f);
        float2 a1 = make_float2(0.f, 0.f);
        float2 a2 = make_float2(0.f, 0.f);
        float2 a3 = make_float2(0.f, 0.f);

        for (int base = beg; base < end; base += 32) {
            const int cnt = min(32, end - base);
            int   s = 0;
            float w = 0.f;
            if (lane < cnt) {
                int2 ent = g_csr[base + lane];
                s = ent.x;
                w = __int_as_float(ent.y);
            }

            int j = 0;
            for (; j + 4 <= cnt; j += 4) {
                int   s0 = __shfl_sync(0xffffffffu, s, j + 0);
                int   s1 = __shfl_sync(0xffffffffu, s, j + 1);
                int   s2 = __shfl_sync(0xffffffffu, s, j + 2);
                int   s3 = __shfl_sync(0xffffffffu, s, j + 3);
                float w0 = __shfl_sync(0xffffffffu, w, j + 0);
                float w1 = __shfl_sync(0xffffffffu, w, j + 1);
                float w2 = __shfl_sync(0xffffffffu, w, j + 2);
                float w3 = __shfl_sync(0xffffffffu, w, j + 3);
                float2 v0 = *reinterpret_cast<const float2*>(
                    x + (size_t)s0 * FDIM + lane * 2);
                float2 v1 = *reinterpret_cast<const float2*>(
                    x + (size_t)s1 * FDIM + lane * 2);
                float2 v2 = *reinterpret_cast<const float2*>(
                    x + (size_t)s2 * FDIM + lane * 2);
                float2 v3 = *reinterpret_cast<const float2*>(
                    x + (size_t)s3 * FDIM + lane * 2);
                a0.x = fmaf(w0, v0.x, a0.x);  a0.y = fmaf(w0, v0.y, a0.y);
                a1.x = fmaf(w1, v1.x, a1.x);  a1.y = fmaf(w1, v1.y, a1.y);
                a2.x = fmaf(w2, v2.x, a2.x);  a2.y = fmaf(w2, v2.y, a2.y);
                a3.x = fmaf(w3, v3.x, a3.x);  a3.y = fmaf(w3, v3.y, a3.y);
            }
            for (; j < cnt; j++) {
                int   sj = __shfl_sync(0xffffffffu, s, j);
                float wj = __shfl_sync(0xffffffffu, w, j);
                float2 v = *reinterpret_cast<const float2*>(
                    x + (size_t)sj * FDIM + lane * 2);
                a0.x = fmaf(wj, v.x, a0.x);
                a0.y = fmaf(wj, v.y, a0.y);
            }
        }

        float2 acc;
        acc.x = (a0.x + a1.x) + (a2.x + a3.x);
        acc.y = (a0.y + a1.y) + (a2.y + a3.y);

        const float di = g_dinv[node];
        float2 sv = *reinterpret_cast<const float2*>(
            x + (size_t)node * FDIM + lane * 2);
        acc.x = fmaf(di, sv.x, acc.x) * di;
        acc.y = fmaf(di, sv.y, acc.y) * di;
        *reinterpret_cast<float2*>(outv + (size_t)node * FDIM + lane * 2) = acc;
    }
}

// ---------------------------------------------------------------------------
// GEMM: C[n,64] = relu(A[n,64] @ W[64,64] + b), fp32.
// 256 threads / 128 rows per block; 4 rows x 8 cols per thread (32 acc).
// Lane map: rbase=(tid>>3)*4 (8 lanes share rows -> LDS broadcast),
//           cg=(tid&7)*8 (8 distinct W addresses -> 128B, 1 wavefront).
// 3 blocks/SM (launch_bounds), 24 warps -> issue-rate bound near FMA peak.
// ---------------------------------------------------------------------------
#define ROWS_PER_BLK 128
#define A_STRIDE4    17

__global__ __launch_bounds__(256, 3) void gemm64_kernel(
    const float* __restrict__ A, const float* __restrict__ W,
    const float* __restrict__ bias, float* __restrict__ C, int n_rows)
{
    extern __shared__ float smem[];
    float*  sW  = smem;                                        // 4096 floats
    float4* sA4 = reinterpret_cast<float4*>(smem + 64 * 64);   // 128*17 float4

    const int tid  = threadIdx.x;
    const int row0 = blockIdx.x * ROWS_PER_BLK;

    for (int i = tid; i < 1024; i += 256)
        reinterpret_cast<float4*>(sW)[i] =
            reinterpret_cast<const float4*>(W)[i];

    for (int i = tid; i < ROWS_PER_BLK * 16; i += 256) {
        int r  = i >> 4;
        int c4 = i & 15;
        int row = row0 + r;
        float4 v = make_float4(0.f, 0.f, 0.f, 0.f);
        if (row < n_rows)
            v = reinterpret_cast<const float4*>(A + (size_t)row * FDIM)[c4];
        sA4[r * A_STRIDE4 + c4] = v;
    }
    __syncthreads();

    const int rbase = (tid >> 3) * 4;   // 0..124 step 4; 8 lanes share -> bcast
    const int cg    = (tid & 7) * 8;    // col base: 0,8,...,56

    float acc[4][8];
#pragma unroll
    for (int r = 0; r < 4; r++)
#pragma unroll
        for (int i = 0; i < 8; i++) acc[r][i] = 0.f;

#pragma unroll
    for (int k4 = 0; k4 < 16; k4++) {
        float4 a[4];
#pragma unroll
        for (int r = 0; r < 4; r++)
            a[r] = sA4[(rbase + r) * A_STRIDE4 + k4];

#pragma unroll
        for (int kk = 0; kk < 4; kk++) {
            const float4* wr = reinterpret_cast<const float4*>(
                sW + (k4 * 4 + kk) * 64 + cg);
            float4 w0 = wr[0], w1 = wr[1];
#pragma unroll
            for (int r = 0; r < 4; r++) {
                float av = (&a[r].x)[kk];
                acc[r][0] = fmaf(av, w0.x, acc[r][0]);
                acc[r][1] = fmaf(av, w0.y, acc[r][1]);
                acc[r][2] = fmaf(av, w0.z, acc[r][2]);
                acc[r][3] = fmaf(av, w0.w, acc[r][3]);
                acc[r][4] = fmaf(av, w1.x, acc[r][4]);
                acc[r][5] = fmaf(av, w1.y, acc[r][5]);
                acc[r][6] = fmaf(av, w1.z, acc[r][6]);
                acc[r][7] = fmaf(av, w1.w, acc[r][7]);
            }
        }
    }

    float4 bv0 = reinterpret_cast<const float4*>(bias + cg)[0];
    float4 bv1 = reinterpret_cast<const float4*>(bias + cg)[1];

#pragma unroll
    for (int r = 0; r < 4; r++) {
        int row = row0 + rbase + r;
        if (row < n_rows) {
            float4* o = reinterpret_cast<float4*>(C + (size_t)row * FDIM + cg);
            o[0] = make_float4(
                fmaxf(acc[r][0] + bv0.x, 0.f), fmaxf(acc[r][1] + bv0.y, 0.f),
                fmaxf(acc[r][2] + bv0.z, 0.f), fmaxf(acc[r][3] + bv0.w, 0.f));
            o[1] = make_float4(
                fmaxf(acc[r][4] + bv1.x, 0.f), fmaxf(acc[r][5] + bv1.y, 0.f),
                fmaxf(acc[r][6] + bv1.z, 0.f), fmaxf(acc[r][7] + bv1.w, 0.f));
        }
    }
}

// ---------------------------------------------------------------------------
extern "C" void kernel_launch(void* const* d_in, const int* in_sizes, int n_in,
                              void* d_out, int out_size)
{
    const float* x  = (const float*)d_in[0];
    const int*   ei = (const int*)d_in[1];     // int32 (JAX x64 disabled)
    const float* W1 = (const float*)d_in[2];
    const float* b1 = (const float*)d_in[3];
    const float* W2 = (const float*)d_in[4];
    const float* b2 = (const float*)d_in[5];
    float* out = (float*)d_out;

    const long long E = (long long)in_sizes[1] / 2;

    float* g_h_ptr;   cudaGetSymbolAddress((void**)&g_h_ptr,   g_h);
    float* g_agg_ptr; cudaGetSymbolAddress((void**)&g_agg_ptr, g_agg);

    const int SMS = 148;
    dim3 blk(256);

    const int GEMM_SMEM = (64 * 64 + ROWS_PER_BLK * A_STRIDE4 * 4) * 4; // 51200 B
    static bool attr_done = false;
    if (!attr_done) {
        cudaFuncSetAttribute(gemm64_kernel,
            cudaFuncAttributeMaxDynamicSharedMemorySize, GEMM_SMEM);
        attr_done = true;
    }

    // ---- CSR build (once per launch, reused by both layers) ----
    zero_deg_kernel<<<(NNODES + 255) / 256, blk>>>();
    hist_kernel<<<SMS * 8, blk>>>(ei, E);
    dinv_kernel<<<(NNODES + 255) / 256, blk>>>();
    scan_reduce_kernel<<<NSCANBLK, SCAN_BLK>>>();
    scan_bsum_kernel<<<1, 128>>>();
    scan_write_kernel<<<NSCANBLK, SCAN_BLK>>>();
    fill_kernel<<<SMS * 8, blk>>>(ei, E);

    const int gemm_grid = (NNODES + ROWS_PER_BLK - 1) / ROWS_PER_BLK;  // 782
    const int agg_grid  = SMS * 24;

    // ---- layer 1:  h1 = relu((Â x) W1 + b1) ----
    agg_kernel<<<agg_grid, blk>>>(x, g_agg_ptr);
    gemm64_kernel<<<gemm_grid, blk, GEMM_SMEM>>>(g_agg_ptr, W1, b1, g_h_ptr, NNODES);

    // ---- layer 2:  out = relu((Â h1) W2 + b2) ----
    agg_kernel<<<agg_grid, blk>>>(g_h_ptr, g_agg_ptr);
    gemm64_kernel<<<gemm_grid, blk, GEMM_SMEM>>>(g_agg_ptr, W2, b2, out, NNODES);
}

// round 10
// speedup vs baseline: 2.0310x; 1.0111x over previous
#include <cuda_runtime.h>
#include <cuda_bf16.h>
#include <stdint.h>

#define NNODES 100000
#define FDIM   64
#define EMAX   2000000   // reference uses E=1.6M; headroom

#define SCAN_BLK   1024
#define NSCANBLK   ((NNODES + SCAN_BLK - 1) / SCAN_BLK)   // 98

// ---------------------------------------------------------------------------
// Static device scratch (no allocation allowed anywhere)
// ---------------------------------------------------------------------------
__device__ __align__(16) float g_h[(size_t)NNODES * FDIM];    // 25.6 MB
__device__ __align__(16) float g_agg[(size_t)NNODES * FDIM];  // 25.6 MB
__device__ float g_dinv[NNODES];
__device__ int   g_degi[NNODES];
__device__ int   g_off[NNODES + 1];
__device__ int   g_cursor[NNODES];
__device__ int   g_bsum[NSCANBLK];
__device__ int   g_bpre[NSCANBLK];
__device__ __align__(8) int2 g_csr[EMAX];   // {src, bitcast(dinv[src])} 16 MB

// packed fp32x2 helpers (sm_100+): bit-identical to scalar fp32 FMA
#define FMA2(acc, a, b) \
    asm("fma.rn.f32x2 %0, %1, %2, %0;" : "+l"(acc) : "l"(a), "l"(b))
#define PACKDUP(d, f) \
    asm("mov.b64 %0, {%1, %1};" : "=l"(d) : "f"(f))
#define UNPACK2(lo, hi, v) \
    asm("mov.b64 {%0, %1}, %2;" : "=f"(lo), "=f"(hi) : "l"(v))

// ---------------------------------------------------------------------------
__global__ void zero_deg_kernel() {
    int i = blockIdx.x * blockDim.x + threadIdx.x;
    if (i < NNODES) g_degi[i] = 0;
}

// histogram of in-edges (int atomics, exact)
__global__ void hist_kernel(const int* __restrict__ ei, long long E) {
    long long stride = (long long)gridDim.x * blockDim.x;
    for (long long e = (long long)blockIdx.x * blockDim.x + threadIdx.x;
         e < E; e += stride)
        atomicAdd(&g_degi[ei[E + e]], 1);
}

__global__ void dinv_kernel() {
    int i = blockIdx.x * blockDim.x + threadIdx.x;
    if (i < NNODES) g_dinv[i] = rsqrtf((float)g_degi[i] + 1.0f);
}

// ---------------------------------------------------------------------------
// Multi-block exclusive scan of g_degi -> g_off (+ cursor copy). 3 phases.
// ---------------------------------------------------------------------------
__global__ __launch_bounds__(SCAN_BLK) void scan_reduce_kernel() {
    __shared__ int sh[SCAN_BLK / 32];
    int i = blockIdx.x * SCAN_BLK + threadIdx.x;
    int v = (i < NNODES) ? g_degi[i] : 0;
#pragma unroll
    for (int o = 16; o > 0; o >>= 1)
        v += __shfl_down_sync(0xffffffffu, v, o);
    if ((threadIdx.x & 31) == 0) sh[threadIdx.x >> 5] = v;
    __syncthreads();
    if (threadIdx.x < 32) {
        int w = (threadIdx.x < SCAN_BLK / 32) ? sh[threadIdx.x] : 0;
#pragma unroll
        for (int o = 16; o > 0; o >>= 1)
            w += __shfl_down_sync(0xffffffffu, w, o);
        if (threadIdx.x == 0) g_bsum[blockIdx.x] = w;
    }
}

__global__ __launch_bounds__(128) void scan_bsum_kernel() {
    __shared__ int sh[128];
    int tid = threadIdx.x;
    int v = (tid < NSCANBLK) ? g_bsum[tid] : 0;
    sh[tid] = v;
    __syncthreads();
    for (int o = 1; o < 128; o <<= 1) {
        int t = (tid >= o) ? sh[tid - o] : 0;
        __syncthreads();
        sh[tid] += t;
        __syncthreads();
    }
    if (tid < NSCANBLK) g_bpre[tid] = sh[tid] - v;   // exclusive
    if (tid == 127) g_off[NNODES] = sh[127];         // total
}

__global__ __launch_bounds__(SCAN_BLK) void scan_write_kernel() {
    __shared__ int sh[SCAN_BLK];
    int tid = threadIdx.x;
    int i = blockIdx.x * SCAN_BLK + tid;
    int v = (i < NNODES) ? g_degi[i] : 0;
    sh[tid] = v;
    __syncthreads();
    for (int o = 1; o < SCAN_BLK; o <<= 1) {
        int t = (tid >= o) ? sh[tid - o] : 0;
        __syncthreads();
        sh[tid] += t;
        __syncthreads();
    }
    if (i < NNODES) {
        int off = g_bpre[blockIdx.x] + sh[tid] - v;  // exclusive
        g_off[i]    = off;
        g_cursor[i] = off;
    }
}

// ---------------------------------------------------------------------------
// CSR fill: csr[pos] = {src, dinv[src]}  (packed 8B write per edge)
// ---------------------------------------------------------------------------
__global__ void fill_kernel(const int* __restrict__ ei, long long E) {
    long long stride = (long long)gridDim.x * blockDim.x;
    for (long long e = (long long)blockIdx.x * blockDim.x + threadIdx.x;
         e < E; e += stride) {
        int s = ei[e];
        int d = ei[E + e];
        int pos = atomicAdd(&g_cursor[d], 1);
        g_csr[pos] = make_int2(s, __float_as_int(g_dinv[s]));
    }
}

// ---------------------------------------------------------------------------
// Aggregation + epilogue: out[node] =
//   relu( dinv[n]*(sum_e dinv[s] x[s] + dinv[n] x[n]) + b )
// One warp per node; each lane owns 2 of the 64 features (float2).
// ---------------------------------------------------------------------------
__global__ __launch_bounds__(256) void agg_kernel(
    const float* __restrict__ x, const float* __restrict__ bias,
    float* __restrict__ outv)
{
    const int lane = threadIdx.x & 31;
    const int gwarp = (blockIdx.x * blockDim.x + threadIdx.x) >> 5;
    const int nwarp = (gridDim.x * blockDim.x) >> 5;

    const float2 bv = reinterpret_cast<const float2*>(bias)[lane];

    for (int node = gwarp; node < NNODES; node += nwarp) {
        const int beg = g_off[node];
        const int end = g_off[node + 1];

        float2 a0 = make_float2(0.f, 0.f);
        float2 a1 = make_float2(0.f, 0.f);
        float2 a2 = make_float2(0.f, 0.f);
        float2 a3 = make_float2(0.f, 0.f);

        for (int base = beg; base < end; base += 32) {
            const int cnt = min(32, end - base);
            int   s = 0;
            float w = 0.f;
            if (lane < cnt) {
                int2 ent = g_csr[base + lane];
                s = ent.x;
                w = __int_as_float(ent.y);
            }

            int j = 0;
            for (; j + 4 <= cnt; j += 4) {
                int   s0 = __shfl_sync(0xffffffffu, s, j + 0);
                int   s1 = __shfl_sync(0xffffffffu, s, j + 1);
                int   s2 = __shfl_sync(0xffffffffu, s, j + 2);
                int   s3 = __shfl_sync(0xffffffffu, s, j + 3);
                float w0 = __shfl_sync(0xffffffffu, w, j + 0);
                float w1 = __shfl_sync(0xffffffffu, w, j + 1);
                float w2 = __shfl_sync(0xffffffffu, w, j + 2);
                float w3 = __shfl_sync(0xffffffffu, w, j + 3);
                float2 v0 = *reinterpret_cast<const float2*>(
                    x + (size_t)s0 * FDIM + lane * 2);
                float2 v1 = *reinterpret_cast<const float2*>(
                    x + (size_t)s1 * FDIM + lane * 2);
                float2 v2 = *reinterpret_cast<const float2*>(
                    x + (size_t)s2 * FDIM + lane * 2);
                float2 v3 = *reinterpret_cast<const float2*>(
                    x + (size_t)s3 * FDIM + lane * 2);
                a0.x = fmaf(w0, v0.x, a0.x);  a0.y = fmaf(w0, v0.y, a0.y);
                a1.x = fmaf(w1, v1.x, a1.x);  a1.y = fmaf(w1, v1.y, a1.y);
                a2.x = fmaf(w2, v2.x, a2.x);  a2.y = fmaf(w2, v2.y, a2.y);
                a3.x = fmaf(w3, v3.x, a3.x);  a3.y = fmaf(w3, v3.y, a3.y);
            }
            for (; j < cnt; j++) {
                int   sj = __shfl_sync(0xffffffffu, s, j);
                float wj = __shfl_sync(0xffffffffu, w, j);
                float2 v = *reinterpret_cast<const float2*>(
                    x + (size_t)sj * FDIM + lane * 2);
                a0.x = fmaf(wj, v.x, a0.x);
                a0.y = fmaf(wj, v.y, a0.y);
            }
        }

        float2 acc;
        acc.x = (a0.x + a1.x) + (a2.x + a3.x);
        acc.y = (a0.y + a1.y) + (a2.y + a3.y);

        const float di = g_dinv[node];
        float2 sv = *reinterpret_cast<const float2*>(
            x + (size_t)node * FDIM + lane * 2);
        acc.x = fmaxf(fmaf(di, sv.x, acc.x) * di + bv.x, 0.f);
        acc.y = fmaxf(fmaf(di, sv.y, acc.y) * di + bv.y, 0.f);
        *reinterpret_cast<float2*>(outv + (size_t)node * FDIM + lane * 2) = acc;
    }
}

// ---------------------------------------------------------------------------
// GEMM (plain): C[n,64] = A[n,64] @ W[64,64], fp32, via packed f32x2 FMA.
// 256 threads / 128 rows per block; 4 rows x 8 cols per thread
// (= 16 packed f32x2 accumulators). 3 blocks/SM.
// ---------------------------------------------------------------------------
#define ROWS_PER_BLK 128
#define A_STRIDE4    17

__global__ __launch_bounds__(256, 3) void gemm64_kernel(
    const float* __restrict__ A, const float* __restrict__ W,
    float* __restrict__ C, int n_rows)
{
    extern __shared__ float smem[];
    float*  sW  = smem;                                        // 4096 floats
    float4* sA4 = reinterpret_cast<float4*>(smem + 64 * 64);   // 128*17 float4

    const int tid  = threadIdx.x;
    const int row0 = blockIdx.x * ROWS_PER_BLK;

    for (int i = tid; i < 1024; i += 256)
        reinterpret_cast<float4*>(sW)[i] =
            reinterpret_cast<const float4*>(W)[i];

    for (int i = tid; i < ROWS_PER_BLK * 16; i += 256) {
        int r  = i >> 4;
        int c4 = i & 15;
        int row = row0 + r;
        float4 v = make_float4(0.f, 0.f, 0.f, 0.f);
        if (row < n_rows)
            v = reinterpret_cast<const float4*>(A + (size_t)row * FDIM)[c4];
        sA4[r * A_STRIDE4 + c4] = v;
    }
    __syncthreads();

    const int rbase = (tid >> 3) * 4;   // 8 lanes share rows -> LDS broadcast
    const int cg    = (tid & 7) * 8;    // col base: 0,8,...,56

    unsigned long long acc2[4][4];      // 4 rows x 4 col-pairs (f32x2)
#pragma unroll
    for (int r = 0; r < 4; r++)
#pragma unroll
        for (int i = 0; i < 4; i++) acc2[r][i] = 0ull;

#pragma unroll
    for (int k4 = 0; k4 < 16; k4++) {
        float4 a[4];
#pragma unroll
        for (int r = 0; r < 4; r++)
            a[r] = sA4[(rbase + r) * A_STRIDE4 + k4];

#pragma unroll
        for (int kk = 0; kk < 4; kk++) {
            const ulonglong2* wr = reinterpret_cast<const ulonglong2*>(
                sW + (k4 * 4 + kk) * 64 + cg);
            ulonglong2 wA = wr[0];      // packed (c0,c1),(c2,c3)
            ulonglong2 wB = wr[1];      // packed (c4,c5),(c6,c7)
#pragma unroll
            for (int r = 0; r < 4; r++) {
                float av = (&a[r].x)[kk];
                unsigned long long av2;
                PACKDUP(av2, av);
                FMA2(acc2[r][0], av2, wA.x);
                FMA2(acc2[r][1], av2, wA.y);
                FMA2(acc2[r][2], av2, wB.x);
                FMA2(acc2[r][3], av2, wB.y);
            }
        }
    }

#pragma unroll
    for (int r = 0; r < 4; r++) {
        int row = row0 + rbase + r;
        if (row < n_rows) {
            float c0, c1, c2, c3, c4, c5, c6, c7;
            UNPACK2(c0, c1, acc2[r][0]);
            UNPACK2(c2, c3, acc2[r][1]);
            UNPACK2(c4, c5, acc2[r][2]);
            UNPACK2(c6, c7, acc2[r][3]);
            float4* o = reinterpret_cast<float4*>(C + (size_t)row * FDIM + cg);
            o[0] = make_float4(c0, c1, c2, c3);
            o[1] = make_float4(c4, c5, c6, c7);
        }
    }
}

// ---------------------------------------------------------------------------
extern "C" void kernel_launch(void* const* d_in, const int* in_sizes, int n_in,
                              void* d_out, int out_size)
{
    const float* x  = (const float*)d_in[0];
    const int*   ei = (const int*)d_in[1];     // int32 (JAX x64 disabled)
    const float* W1 = (const float*)d_in[2];
    const float* b1 = (const float*)d_in[3];
    const float* W2 = (const float*)d_in[4];
    const float* b2 = (const float*)d_in[5];
    float* out = (float*)d_out;

    const long long E = (long long)in_sizes[1] / 2;

    float* g_h_ptr;   cudaGetSymbolAddress((void**)&g_h_ptr,   g_h);
    float* g_agg_ptr; cudaGetSymbolAddress((void**)&g_agg_ptr, g_agg);

    const int SMS = 148;
    dim3 blk(256);

    const int GEMM_SMEM = (64 * 64 + ROWS_PER_BLK * A_STRIDE4 * 4) * 4; // 51200 B

    // One-time host-side setup (like attr_done): attrs + side stream/events.
    static cudaStream_t s_side = nullptr;
    static cudaEvent_t  ev_fork = nullptr, ev_join = nullptr;
    static bool init_done = false;
    if (!init_done) {
        cudaFuncSetAttribute(gemm64_kernel,
            cudaFuncAttributeMaxDynamicSharedMemorySize, GEMM_SMEM);
        cudaStreamCreateWithFlags(&s_side, cudaStreamNonBlocking);
        cudaEventCreateWithFlags(&ev_fork, cudaEventDisableTiming);
        cudaEventCreateWithFlags(&ev_join, cudaEventDisableTiming);
        init_done = true;
    }
    const bool overlap = (s_side != nullptr) && ev_fork && ev_join;

    const int gemm_grid = (NNODES + ROWS_PER_BLK - 1) / ROWS_PER_BLK;  // 782
    const int agg_grid  = SMS * 24;

    cudaStream_t sb = overlap ? s_side : (cudaStream_t)0;

    if (overlap) cudaEventRecord(ev_fork, 0);

    // ---- GEMM-1 (no CSR dependency): g_h = x @ W1 ----
    gemm64_kernel<<<gemm_grid, blk, GEMM_SMEM>>>(x, W1, g_h_ptr, NNODES);

    // ---- CSR build on side stream (concurrent with GEMM-1) ----
    if (overlap) cudaStreamWaitEvent(sb, ev_fork, 0);
    zero_deg_kernel<<<(NNODES + 255) / 256, blk, 0, sb>>>();
    hist_kernel<<<SMS * 8, blk, 0, sb>>>(ei, E);
    dinv_kernel<<<(NNODES + 255) / 256, blk, 0, sb>>>();
    scan_reduce_kernel<<<NSCANBLK, SCAN_BLK, 0, sb>>>();
    scan_bsum_kernel<<<1, 128, 0, sb>>>();
    scan_write_kernel<<<NSCANBLK, SCAN_BLK, 0, sb>>>();
    fill_kernel<<<SMS * 8, blk, 0, sb>>>(ei, E);
    if (overlap) {
        cudaEventRecord(ev_join, sb);
        cudaStreamWaitEvent(0, ev_join, 0);
    }

    // ---- layer 1 aggregate + bias + relu:  g_agg = relu(Â g_h + b1) ----
    agg_kernel<<<agg_grid, blk>>>(g_h_ptr, b1, g_agg_ptr);

    // ---- GEMM-2: g_h = g_agg @ W2 ----
    gemm64_kernel<<<gemm_grid, blk, GEMM_SMEM>>>(g_agg_ptr, W2, g_h_ptr, NNODES);

    // ---- layer 2 aggregate + bias + relu:  out = relu(Â g_h + b2) ----
    agg_kernel<<<agg_grid, blk>>>(g_h_ptr, b2, out);
}

// round 11
// speedup vs baseline: 2.1266x; 1.0471x over previous
#include <cuda_runtime.h>
#include <cuda_fp16.h>
#include <stdint.h>

#define NNODES 100000
#define FDIM   64
#define EMAX   2000000   // reference uses E=1.6M; headroom

#define SCAN_BLK   1024
#define NSCANBLK   ((NNODES + SCAN_BLK - 1) / SCAN_BLK)   // 98

// ---------------------------------------------------------------------------
// Static device scratch (no allocation allowed anywhere)
// ---------------------------------------------------------------------------
__device__ __align__(16) __half g_hh[(size_t)NNODES * FDIM];  // 12.8 MB (h, fp16)
__device__ __align__(16) float  g_agg[(size_t)NNODES * FDIM]; // 25.6 MB (fp32)
__device__ float g_dinv[NNODES];
__device__ int   g_degi[NNODES];
__device__ int   g_off[NNODES + 1];
__device__ int   g_cursor[NNODES];
__device__ int   g_bsum[NSCANBLK];
__device__ int   g_bpre[NSCANBLK];
__device__ __align__(8) int2 g_csr[EMAX];   // {src, bitcast(dinv[src])} 16 MB

// packed fp32x2 helpers (sm_100+): bit-identical to scalar fp32 FMA
#define FMA2(acc, a, b) \
    asm("fma.rn.f32x2 %0, %1, %2, %0;" : "+l"(acc) : "l"(a), "l"(b))
#define PACKDUP(d, f) \
    asm("mov.b64 %0, {%1, %1};" : "=l"(d) : "f"(f))
#define UNPACK2(lo, hi, v) \
    asm("mov.b64 {%0, %1}, %2;" : "=f"(lo), "=f"(hi) : "l"(v))

// ---------------------------------------------------------------------------
// histogram of in-edges (int atomics, exact). edge_index int32, [2, E].
// ---------------------------------------------------------------------------
__global__ void hist_kernel(const int* __restrict__ ei, long long E) {
    long long stride = (long long)gridDim.x * blockDim.x;
    for (long long e = (long long)blockIdx.x * blockDim.x + threadIdx.x;
         e < E; e += stride)
        atomicAdd(&g_degi[ei[E + e]], 1);
}

// ---------------------------------------------------------------------------
// Multi-block exclusive scan of g_degi -> g_off (+ cursor copy). 3 phases.
// Phase 1 also computes dinv (reads degi anyway).
// ---------------------------------------------------------------------------
__global__ __launch_bounds__(SCAN_BLK) void scan_reduce_kernel() {
    __shared__ int sh[SCAN_BLK / 32];
    int i = blockIdx.x * SCAN_BLK + threadIdx.x;
    int v = 0;
    if (i < NNODES) {
        v = g_degi[i];
        g_dinv[i] = rsqrtf((float)v + 1.0f);   // fused dinv
    }
    int r = v;
#pragma unroll
    for (int o = 16; o > 0; o >>= 1)
        r += __shfl_down_sync(0xffffffffu, r, o);
    if ((threadIdx.x & 31) == 0) sh[threadIdx.x >> 5] = r;
    __syncthreads();
    if (threadIdx.x < 32) {
        int w = (threadIdx.x < SCAN_BLK / 32) ? sh[threadIdx.x] : 0;
#pragma unroll
        for (int o = 16; o > 0; o >>= 1)
            w += __shfl_down_sync(0xffffffffu, w, o);
        if (threadIdx.x == 0) g_bsum[blockIdx.x] = w;
    }
}

__global__ __launch_bounds__(128) void scan_bsum_kernel() {
    __shared__ int sh[128];
    int tid = threadIdx.x;
    int v = (tid < NSCANBLK) ? g_bsum[tid] : 0;
    sh[tid] = v;
    __syncthreads();
    for (int o = 1; o < 128; o <<= 1) {
        int t = (tid >= o) ? sh[tid - o] : 0;
        __syncthreads();
        sh[tid] += t;
        __syncthreads();
    }
    if (tid < NSCANBLK) g_bpre[tid] = sh[tid] - v;   // exclusive
    if (tid == 127) g_off[NNODES] = sh[127];         // total
}

__global__ __launch_bounds__(SCAN_BLK) void scan_write_kernel() {
    __shared__ int sh[SCAN_BLK];
    int tid = threadIdx.x;
    int i = blockIdx.x * SCAN_BLK + tid;
    int v = (i < NNODES) ? g_degi[i] : 0;
    sh[tid] = v;
    __syncthreads();
    for (int o = 1; o < SCAN_BLK; o <<= 1) {
        int t = (tid >= o) ? sh[tid - o] : 0;
        __syncthreads();
        sh[tid] += t;
        __syncthreads();
    }
    if (i < NNODES) {
        int off = g_bpre[blockIdx.x] + sh[tid] - v;  // exclusive
        g_off[i]    = off;
        g_cursor[i] = off;
    }
}

// ---------------------------------------------------------------------------
// CSR fill: csr[pos] = {src, dinv[src]}  (packed 8B write per edge)
// ---------------------------------------------------------------------------
__global__ void fill_kernel(const int* __restrict__ ei, long long E) {
    long long stride = (long long)gridDim.x * blockDim.x;
    for (long long e = (long long)blockIdx.x * blockDim.x + threadIdx.x;
         e < E; e += stride) {
        int s = ei[e];
        int d = ei[E + e];
        int pos = atomicAdd(&g_cursor[d], 1);
        g_csr[pos] = make_int2(s, __float_as_int(g_dinv[s]));
    }
}

// ---------------------------------------------------------------------------
// Aggregation + epilogue (fp16 gather, fp32 accumulate):
//   out[node] = relu( dinv[n]*(sum_e dinv[s] h[s] + dinv[n] h[n]) + b )
// One warp per node; each lane owns 2 of the 64 features (one half2).
// Gather traffic: 128 B/edge (vs 256 fp32).
// ---------------------------------------------------------------------------
template <typename OutT>
__global__ __launch_bounds__(256) void agg_kernel(
    const __half* __restrict__ h, const float* __restrict__ bias,
    OutT* __restrict__ outv)
{
    const int lane = threadIdx.x & 31;
    const int gwarp = (blockIdx.x * blockDim.x + threadIdx.x) >> 5;
    const int nwarp = (gridDim.x * blockDim.x) >> 5;

    const float2 bv = reinterpret_cast<const float2*>(bias)[lane];

    for (int node = gwarp; node < NNODES; node += nwarp) {
        const int beg = g_off[node];
        const int end = g_off[node + 1];

        float2 a0 = make_float2(0.f, 0.f);
        float2 a1 = make_float2(0.f, 0.f);
        float2 a2 = make_float2(0.f, 0.f);
        float2 a3 = make_float2(0.f, 0.f);

        for (int base = beg; base < end; base += 32) {
            const int cnt = min(32, end - base);
            int   s = 0;
            float w = 0.f;
            if (lane < cnt) {
                int2 ent = g_csr[base + lane];
                s = ent.x;
                w = __int_as_float(ent.y);
            }

            int j = 0;
            for (; j + 4 <= cnt; j += 4) {
                int   s0 = __shfl_sync(0xffffffffu, s, j + 0);
                int   s1 = __shfl_sync(0xffffffffu, s, j + 1);
                int   s2 = __shfl_sync(0xffffffffu, s, j + 2);
                int   s3 = __shfl_sync(0xffffffffu, s, j + 3);
                float w0 = __shfl_sync(0xffffffffu, w, j + 0);
                float w1 = __shfl_sync(0xffffffffu, w, j + 1);
                float w2 = __shfl_sync(0xffffffffu, w, j + 2);
                float w3 = __shfl_sync(0xffffffffu, w, j + 3);
                float2 v0 = __half22float2(*reinterpret_cast<const __half2*>(
                    h + (size_t)s0 * FDIM + lane * 2));
                float2 v1 = __half22float2(*reinterpret_cast<const __half2*>(
                    h + (size_t)s1 * FDIM + lane * 2));
                float2 v2 = __half22float2(*reinterpret_cast<const __half2*>(
                    h + (size_t)s2 * FDIM + lane * 2));
                float2 v3 = __half22float2(*reinterpret_cast<const __half2*>(
                    h + (size_t)s3 * FDIM + lane * 2));
                a0.x = fmaf(w0, v0.x, a0.x);  a0.y = fmaf(w0, v0.y, a0.y);
                a1.x = fmaf(w1, v1.x, a1.x);  a1.y = fmaf(w1, v1.y, a1.y);
                a2.x = fmaf(w2, v2.x, a2.x);  a2.y = fmaf(w2, v2.y, a2.y);
                a3.x = fmaf(w3, v3.x, a3.x);  a3.y = fmaf(w3, v3.y, a3.y);
            }
            for (; j < cnt; j++) {
                int   sj = __shfl_sync(0xffffffffu, s, j);
                float wj = __shfl_sync(0xffffffffu, w, j);
                float2 v = __half22float2(*reinterpret_cast<const __half2*>(
                    h + (size_t)sj * FDIM + lane * 2));
                a0.x = fmaf(wj, v.x, a0.x);
                a0.y = fmaf(wj, v.y, a0.y);
            }
        }

        float2 acc;
        acc.x = (a0.x + a1.x) + (a2.x + a3.x);
        acc.y = (a0.y + a1.y) + (a2.y + a3.y);

        const float di = g_dinv[node];
        float2 sv = __half22float2(*reinterpret_cast<const __half2*>(
            h + (size_t)node * FDIM + lane * 2));
        acc.x = fmaxf(fmaf(di, sv.x, acc.x) * di + bv.x, 0.f);
        acc.y = fmaxf(fmaf(di, sv.y, acc.y) * di + bv.y, 0.f);
        *reinterpret_cast<float2*>(outv + (size_t)node * FDIM + lane * 2) = acc;
    }
}

// ---------------------------------------------------------------------------
// GEMM: C[n,64] = A[n,64] @ W[64,64]  (fp32 math via packed f32x2 FMA,
// fp16 output). 256 threads / 128 rows per block; 4 rows x 8 cols / thread.
// ---------------------------------------------------------------------------
#define ROWS_PER_BLK 128
#define A_STRIDE4    17

__global__ __launch_bounds__(256, 3) void gemm64_kernel(
    const float* __restrict__ A, const float* __restrict__ W,
    __half* __restrict__ C, int n_rows)
{
    extern __shared__ float smem[];
    float*  sW  = smem;                                        // 4096 floats
    float4* sA4 = reinterpret_cast<float4*>(smem + 64 * 64);   // 128*17 float4

    const int tid  = threadIdx.x;
    const int row0 = blockIdx.x * ROWS_PER_BLK;

    for (int i = tid; i < 1024; i += 256)
        reinterpret_cast<float4*>(sW)[i] =
            reinterpret_cast<const float4*>(W)[i];

    for (int i = tid; i < ROWS_PER_BLK * 16; i += 256) {
        int r  = i >> 4;
        int c4 = i & 15;
        int row = row0 + r;
        float4 v = make_float4(0.f, 0.f, 0.f, 0.f);
        if (row < n_rows)
            v = reinterpret_cast<const float4*>(A + (size_t)row * FDIM)[c4];
        sA4[r * A_STRIDE4 + c4] = v;
    }
    __syncthreads();

    const int rbase = (tid >> 3) * 4;   // 8 lanes share rows -> LDS broadcast
    const int cg    = (tid & 7) * 8;    // col base: 0,8,...,56

    unsigned long long acc2[4][4];      // 4 rows x 4 col-pairs (f32x2)
#pragma unroll
    for (int r = 0; r < 4; r++)
#pragma unroll
        for (int i = 0; i < 4; i++) acc2[r][i] = 0ull;

#pragma unroll
    for (int k4 = 0; k4 < 16; k4++) {
        float4 a[4];
#pragma unroll
        for (int r = 0; r < 4; r++)
            a[r] = sA4[(rbase + r) * A_STRIDE4 + k4];

#pragma unroll
        for (int kk = 0; kk < 4; kk++) {
            const ulonglong2* wr = reinterpret_cast<const ulonglong2*>(
                sW + (k4 * 4 + kk) * 64 + cg);
            ulonglong2 wA = wr[0];
            ulonglong2 wB = wr[1];
#pragma unroll
            for (int r = 0; r < 4; r++) {
                float av = (&a[r].x)[kk];
                unsigned long long av2;
                PACKDUP(av2, av);
                FMA2(acc2[r][0], av2, wA.x);
                FMA2(acc2[r][1], av2, wA.y);
                FMA2(acc2[r][2], av2, wB.x);
                FMA2(acc2[r][3], av2, wB.y);
            }
        }
    }

#pragma unroll
    for (int r = 0; r < 4; r++) {
        int row = row0 + rbase + r;
        if (row < n_rows) {
            float c0, c1, c2, c3, c4, c5, c6, c7;
            UNPACK2(c0, c1, acc2[r][0]);
            UNPACK2(c2, c3, acc2[r][1]);
            UNPACK2(c4, c5, acc2[r][2]);
            UNPACK2(c6, c7, acc2[r][3]);
            union { __half2 h[4]; uint4 u; } p;
            p.h[0] = __floats2half2_rn(c0, c1);
            p.h[1] = __floats2half2_rn(c2, c3);
            p.h[2] = __floats2half2_rn(c4, c5);
            p.h[3] = __floats2half2_rn(c6, c7);
            *reinterpret_cast<uint4*>(C + (size_t)row * FDIM + cg) = p.u;
        }
    }
}

// ---------------------------------------------------------------------------
extern "C" void kernel_launch(void* const* d_in, const int* in_sizes, int n_in,
                              void* d_out, int out_size)
{
    const float* x  = (const float*)d_in[0];
    const int*   ei = (const int*)d_in[1];     // int32 (JAX x64 disabled)
    const float* W1 = (const float*)d_in[2];
    const float* b1 = (const float*)d_in[3];
    const float* W2 = (const float*)d_in[4];
    const float* b2 = (const float*)d_in[5];
    float* out = (float*)d_out;

    const long long E = (long long)in_sizes[1] / 2;

    __half* g_hh_ptr;  cudaGetSymbolAddress((void**)&g_hh_ptr,  g_hh);
    float*  g_agg_ptr; cudaGetSymbolAddress((void**)&g_agg_ptr, g_agg);
    int*    g_degi_ptr; cudaGetSymbolAddress((void**)&g_degi_ptr, g_degi);

    const int SMS = 148;
    dim3 blk(256);

    const int GEMM_SMEM = (64 * 64 + ROWS_PER_BLK * A_STRIDE4 * 4) * 4; // 51200 B
    static bool attr_done = false;
    if (!attr_done) {
        cudaFuncSetAttribute(gemm64_kernel,
            cudaFuncAttributeMaxDynamicSharedMemorySize, GEMM_SMEM);
        attr_done = true;
    }

    const int gemm_grid = (NNODES + ROWS_PER_BLK - 1) / ROWS_PER_BLK;  // 782
    const int agg_grid  = SMS * 24;

    // ---- CSR build ----
    cudaMemsetAsync(g_degi_ptr, 0, NNODES * sizeof(int));
    hist_kernel<<<SMS * 8, blk>>>(ei, E);
    scan_reduce_kernel<<<NSCANBLK, SCAN_BLK>>>();   // also computes dinv
    scan_bsum_kernel<<<1, 128>>>();
    scan_write_kernel<<<NSCANBLK, SCAN_BLK>>>();
    fill_kernel<<<SMS * 8, blk>>>(ei, E);

    // ---- layer 1 ----
    gemm64_kernel<<<gemm_grid, blk, GEMM_SMEM>>>(x, W1, g_hh_ptr, NNODES);
    agg_kernel<float><<<agg_grid, blk>>>(g_hh_ptr, b1, g_agg_ptr);

    // ---- layer 2 ----
    gemm64_kernel<<<gemm_grid, blk, GEMM_SMEM>>>(g_agg_ptr, W2, g_hh_ptr, NNODES);
    agg_kernel<float><<<agg_grid, blk>>>(g_hh_ptr, b2, out);
}

// round 12
// speedup vs baseline: 2.2884x; 1.0761x over previous
#include <cuda_runtime.h>
#include <cuda_fp16.h>
#include <stdint.h>

#define NNODES 100000
#define FDIM   64
#define EMAX   2000000   // reference uses E=1.6M; headroom

#define SCAN_BLK   1024
#define NSCANBLK   ((NNODES + SCAN_BLK - 1) / SCAN_BLK)   // 98

// ---------------------------------------------------------------------------
// Static device scratch (no allocation allowed anywhere)
// ---------------------------------------------------------------------------
__device__ __align__(16) __half g_hh[(size_t)NNODES * FDIM];  // 12.8 MB (h, fp16)
__device__ __align__(16) __half g_ah[(size_t)NNODES * FDIM];  // 12.8 MB (act, fp16)
__device__ float g_dinv[NNODES];
__device__ int   g_degi[NNODES];
__device__ int   g_off[NNODES + 1];
__device__ int   g_cursor[NNODES];
__device__ int   g_bsum[NSCANBLK];
__device__ int   g_bpre[NSCANBLK];
__device__ __align__(16) int2 g_csr[EMAX];  // {src, bitcast(dinv[src])} 16 MB

// packed fp32x2 helpers (sm_100+): bit-identical to scalar fp32 FMA
#define FMA2(acc, a, b) \
    asm("fma.rn.f32x2 %0, %1, %2, %0;" : "+l"(acc) : "l"(a), "l"(b))
#define PACKDUP(d, f) \
    asm("mov.b64 %0, {%1, %1};" : "=l"(d) : "f"(f))
#define UNPACK2(lo, hi, v) \
    asm("mov.b64 {%0, %1}, %2;" : "=f"(lo), "=f"(hi) : "l"(v))

// ---------------------------------------------------------------------------
// histogram of in-edges (int atomics, exact). edge_index int32, [2, E].
// ---------------------------------------------------------------------------
__global__ void hist_kernel(const int* __restrict__ ei, long long E) {
    long long stride = (long long)gridDim.x * blockDim.x;
    for (long long e = (long long)blockIdx.x * blockDim.x + threadIdx.x;
         e < E; e += stride)
        atomicAdd(&g_degi[ei[E + e]], 1);
}

// ---------------------------------------------------------------------------
// Multi-block exclusive scan of g_degi -> g_off (+ cursor copy). 3 phases.
// Phase 1 also computes dinv (reads degi anyway).
// ---------------------------------------------------------------------------
__global__ __launch_bounds__(SCAN_BLK) void scan_reduce_kernel() {
    __shared__ int sh[SCAN_BLK / 32];
    int i = blockIdx.x * SCAN_BLK + threadIdx.x;
    int v = 0;
    if (i < NNODES) {
        v = g_degi[i];
        g_dinv[i] = rsqrtf((float)v + 1.0f);   // fused dinv
    }
    int r = v;
#pragma unroll
    for (int o = 16; o > 0; o >>= 1)
        r += __shfl_down_sync(0xffffffffu, r, o);
    if ((threadIdx.x & 31) == 0) sh[threadIdx.x >> 5] = r;
    __syncthreads();
    if (threadIdx.x < 32) {
        int w = (threadIdx.x < SCAN_BLK / 32) ? sh[threadIdx.x] : 0;
#pragma unroll
        for (int o = 16; o > 0; o >>= 1)
            w += __shfl_down_sync(0xffffffffu, w, o);
        if (threadIdx.x == 0) g_bsum[blockIdx.x] = w;
    }
}

__global__ __launch_bounds__(128) void scan_bsum_kernel() {
    __shared__ int sh[128];
    int tid = threadIdx.x;
    int v = (tid < NSCANBLK) ? g_bsum[tid] : 0;
    sh[tid] = v;
    __syncthreads();
    for (int o = 1; o < 128; o <<= 1) {
        int t = (tid >= o) ? sh[tid - o] : 0;
        __syncthreads();
        sh[tid] += t;
        __syncthreads();
    }
    if (tid < NSCANBLK) g_bpre[tid] = sh[tid] - v;   // exclusive
    if (tid == 127) g_off[NNODES] = sh[127];         // total
}

__global__ __launch_bounds__(SCAN_BLK) void scan_write_kernel() {
    __shared__ int sh[SCAN_BLK];
    int tid = threadIdx.x;
    int i = blockIdx.x * SCAN_BLK + tid;
    int v = (i < NNODES) ? g_degi[i] : 0;
    sh[tid] = v;
    __syncthreads();
    for (int o = 1; o < SCAN_BLK; o <<= 1) {
        int t = (tid >= o) ? sh[tid - o] : 0;
        __syncthreads();
        sh[tid] += t;
        __syncthreads();
    }
    if (i < NNODES) {
        int off = g_bpre[blockIdx.x] + sh[tid] - v;  // exclusive
        g_off[i]    = off;
        g_cursor[i] = off;
    }
}

// ---------------------------------------------------------------------------
// CSR fill: csr[pos] = {src, dinv[src]}  (packed 8B write per edge)
// ---------------------------------------------------------------------------
__global__ void fill_kernel(const int* __restrict__ ei, long long E) {
    long long stride = (long long)gridDim.x * blockDim.x;
    for (long long e = (long long)blockIdx.x * blockDim.x + threadIdx.x;
         e < E; e += stride) {
        int s = ei[e];
        int d = ei[E + e];
        int pos = atomicAdd(&g_cursor[d], 1);
        g_csr[pos] = make_int2(s, __float_as_int(g_dinv[s]));
    }
}

// ---------------------------------------------------------------------------
// Aggregation + epilogue (fp16 gather, fp32 accumulate):
//   out[node] = relu( dinv[n]*(sum_e dinv[s] h[s] + dinv[n] h[n]) + b )
// One warp per node; warp split into 4 quarters (eq = lane>>3), each quarter
// owns one edge per step; each of its 8 lanes loads uint4 = 8 halves (16B)
// -> one LDG.128 moves a whole 128B edge row, 4 edges per load instruction.
// Butterfly reduce across quarters at the end; 8 lanes write the row.
// ---------------------------------------------------------------------------
template <typename OutT>
__global__ __launch_bounds__(256) void agg_kernel(
    const __half* __restrict__ h, const float* __restrict__ bias,
    OutT* __restrict__ outv)
{
    const int lane = threadIdx.x & 31;
    const int eq   = lane >> 3;     // edge slot within quad: 0..3
    const int fl   = lane & 7;      // feature octet: halves [fl*8, fl*8+8)
    const int gwarp = (blockIdx.x * blockDim.x + threadIdx.x) >> 5;
    const int nwarp = (gridDim.x * blockDim.x) >> 5;

    const float4 b0 = reinterpret_cast<const float4*>(bias)[fl * 2];
    const float4 b1 = reinterpret_cast<const float4*>(bias)[fl * 2 + 1];

    for (int node = gwarp; node < NNODES; node += nwarp) {
        const int beg = g_off[node];
        const int end = g_off[node + 1];
        const float di = g_dinv[node];

        float acc[8];
        // self-loop handled by quarter 0 (weight di, times di later)
        if (eq == 0) {
            uint4 sv = *reinterpret_cast<const uint4*>(
                h + (size_t)node * FDIM + fl * 8);
            const __half2* hp = reinterpret_cast<const __half2*>(&sv);
#pragma unroll
            for (int p = 0; p < 4; p++) {
                float2 f = __half22float2(hp[p]);
                acc[2 * p]     = di * f.x;
                acc[2 * p + 1] = di * f.y;
            }
        } else {
#pragma unroll
            for (int p = 0; p < 8; p++) acc[p] = 0.f;
        }

        int base = beg;
        // main loop: 8 edges per iteration, 2 independent LDG.128 chains
        for (; base + 8 <= end; base += 8) {
            int2 e0 = g_csr[base + eq];
            int2 e1 = g_csr[base + 4 + eq];
            uint4 v0 = *reinterpret_cast<const uint4*>(
                h + (size_t)e0.x * FDIM + fl * 8);
            uint4 v1 = *reinterpret_cast<const uint4*>(
                h + (size_t)e1.x * FDIM + fl * 8);
            float w0 = __int_as_float(e0.y);
            float w1 = __int_as_float(e1.y);
            const __half2* p0 = reinterpret_cast<const __half2*>(&v0);
            const __half2* p1 = reinterpret_cast<const __half2*>(&v1);
#pragma unroll
            for (int p = 0; p < 4; p++) {
                float2 f0 = __half22float2(p0[p]);
                float2 f1 = __half22float2(p1[p]);
                acc[2 * p]     = fmaf(w0, f0.x, acc[2 * p]);
                acc[2 * p + 1] = fmaf(w0, f0.y, acc[2 * p + 1]);
                acc[2 * p]     = fmaf(w1, f1.x, acc[2 * p]);
                acc[2 * p + 1] = fmaf(w1, f1.y, acc[2 * p + 1]);
            }
        }
        // remainder: up to 7 edges, 4 at a time with zero-weight padding
        for (; base < end; base += 4) {
            int idx = base + eq;
            int2 e0 = g_csr[idx < end ? idx : (end - 1)];
            float w0 = (idx < end) ? __int_as_float(e0.y) : 0.f;
            uint4 v0 = *reinterpret_cast<const uint4*>(
                h + (size_t)e0.x * FDIM + fl * 8);
            const __half2* p0 = reinterpret_cast<const __half2*>(&v0);
#pragma unroll
            for (int p = 0; p < 4; p++) {
                float2 f0 = __half22float2(p0[p]);
                acc[2 * p]     = fmaf(w0, f0.x, acc[2 * p]);
                acc[2 * p + 1] = fmaf(w0, f0.y, acc[2 * p + 1]);
            }
        }

        // butterfly-reduce across the 4 quarters (xor 8, xor 16)
#pragma unroll
        for (int p = 0; p < 8; p++) {
            acc[p] += __shfl_xor_sync(0xffffffffu, acc[p], 8);
            acc[p] += __shfl_xor_sync(0xffffffffu, acc[p], 16);
        }

        if (eq == 0) {   // lanes 0..7 write the 64-float row
            float r[8];
            r[0] = fmaxf(fmaf(acc[0], di, b0.x), 0.f);
            r[1] = fmaxf(fmaf(acc[1], di, b0.y), 0.f);
            r[2] = fmaxf(fmaf(acc[2], di, b0.z), 0.f);
            r[3] = fmaxf(fmaf(acc[3], di, b0.w), 0.f);
            r[4] = fmaxf(fmaf(acc[4], di, b1.x), 0.f);
            r[5] = fmaxf(fmaf(acc[5], di, b1.y), 0.f);
            r[6] = fmaxf(fmaf(acc[6], di, b1.z), 0.f);
            r[7] = fmaxf(fmaf(acc[7], di, b1.w), 0.f);
            if constexpr (sizeof(OutT) == 2) {   // fp16 activations
                union { __half2 hx[4]; uint4 u; } pk;
                pk.hx[0] = __floats2half2_rn(r[0], r[1]);
                pk.hx[1] = __floats2half2_rn(r[2], r[3]);
                pk.hx[2] = __floats2half2_rn(r[4], r[5]);
                pk.hx[3] = __floats2half2_rn(r[6], r[7]);
                *reinterpret_cast<uint4*>(
                    (__half*)outv + (size_t)node * FDIM + fl * 8) = pk.u;
            } else {                             // fp32 final output
                float4* o = reinterpret_cast<float4*>(
                    (float*)outv + (size_t)node * FDIM + fl * 8);
                o[0] = make_float4(r[0], r[1], r[2], r[3]);
                o[1] = make_float4(r[4], r[5], r[6], r[7]);
            }
        }
    }
}

// ---------------------------------------------------------------------------
// GEMM: C[n,64] = A[n,64] @ W[64,64]  (fp32 math via packed f32x2 FMA,
// fp16 output; A may be fp32 or fp16). 256 thr / 128 rows; 4r x 8c / thread.
// ---------------------------------------------------------------------------
#define ROWS_PER_BLK 128
#define A_STRIDE4    17

template <typename InT>
__global__ __launch_bounds__(256, 3) void gemm64_kernel(
    const InT* __restrict__ A, const float* __restrict__ W,
    __half* __restrict__ C, int n_rows)
{
    extern __shared__ float smem[];
    float*  sW  = smem;                                        // 4096 floats
    float4* sA4 = reinterpret_cast<float4*>(smem + 64 * 64);   // 128*17 float4

    const int tid  = threadIdx.x;
    const int row0 = blockIdx.x * ROWS_PER_BLK;

    for (int i = tid; i < 1024; i += 256)
        reinterpret_cast<float4*>(sW)[i] =
            reinterpret_cast<const float4*>(W)[i];

    for (int i = tid; i < ROWS_PER_BLK * 16; i += 256) {
        int r  = i >> 4;
        int c4 = i & 15;
        int row = row0 + r;
        float4 v = make_float4(0.f, 0.f, 0.f, 0.f);
        if (row < n_rows) {
            if constexpr (sizeof(InT) == 2) {
                uint2 raw = *reinterpret_cast<const uint2*>(
                    reinterpret_cast<const __half*>(A)
                    + (size_t)row * FDIM + c4 * 4);
                float2 f0 = __half22float2(
                    *reinterpret_cast<const __half2*>(&raw.x));
                float2 f1 = __half22float2(
                    *reinterpret_cast<const __half2*>(&raw.y));
                v = make_float4(f0.x, f0.y, f1.x, f1.y);
            } else {
                v = reinterpret_cast<const float4*>(
                        (const float*)A + (size_t)row * FDIM)[c4];
            }
        }
        sA4[r * A_STRIDE4 + c4] = v;
    }
    __syncthreads();

    const int rbase = (tid >> 3) * 4;   // 8 lanes share rows -> LDS broadcast
    const int cg    = (tid & 7) * 8;    // col base: 0,8,...,56

    unsigned long long acc2[4][4];      // 4 rows x 4 col-pairs (f32x2)
#pragma unroll
    for (int r = 0; r < 4; r++)
#pragma unroll
        for (int i = 0; i < 4; i++) acc2[r][i] = 0ull;

#pragma unroll
    for (int k4 = 0; k4 < 16; k4++) {
        float4 a[4];
#pragma unroll
        for (int r = 0; r < 4; r++)
            a[r] = sA4[(rbase + r) * A_STRIDE4 + k4];

#pragma unroll
        for (int kk = 0; kk < 4; kk++) {
            const ulonglong2* wr = reinterpret_cast<const ulonglong2*>(
                sW + (k4 * 4 + kk) * 64 + cg);
            ulonglong2 wA = wr[0];
            ulonglong2 wB = wr[1];
#pragma unroll
            for (int r = 0; r < 4; r++) {
                float av = (&a[r].x)[kk];
                unsigned long long av2;
                PACKDUP(av2, av);
                FMA2(acc2[r][0], av2, wA.x);
                FMA2(acc2[r][1], av2, wA.y);
                FMA2(acc2[r][2], av2, wB.x);
                FMA2(acc2[r][3], av2, wB.y);
            }
        }
    }

#pragma unroll
    for (int r = 0; r < 4; r++) {
        int row = row0 + rbase + r;
        if (row < n_rows) {
            float c0, c1, c2, c3, c4, c5, c6, c7;
            UNPACK2(c0, c1, acc2[r][0]);
            UNPACK2(c2, c3, acc2[r][1]);
            UNPACK2(c4, c5, acc2[r][2]);
            UNPACK2(c6, c7, acc2[r][3]);
            union { __half2 h[4]; uint4 u; } p;
            p.h[0] = __floats2half2_rn(c0, c1);
            p.h[1] = __floats2half2_rn(c2, c3);
            p.h[2] = __floats2half2_rn(c4, c5);
            p.h[3] = __floats2half2_rn(c6, c7);
            *reinterpret_cast<uint4*>(C + (size_t)row * FDIM + cg) = p.u;
        }
    }
}

// ---------------------------------------------------------------------------
extern "C" void kernel_launch(void* const* d_in, const int* in_sizes, int n_in,
                              void* d_out, int out_size)
{
    const float* x  = (const float*)d_in[0];
    const int*   ei = (const int*)d_in[1];     // int32 (JAX x64 disabled)
    const float* W1 = (const float*)d_in[2];
    const float* b1 = (const float*)d_in[3];
    const float* W2 = (const float*)d_in[4];
    const float* b2 = (const float*)d_in[5];
    float* out = (float*)d_out;

    const long long E = (long long)in_sizes[1] / 2;

    __half* g_hh_ptr;  cudaGetSymbolAddress((void**)&g_hh_ptr,  g_hh);
    __half* g_ah_ptr;  cudaGetSymbolAddress((void**)&g_ah_ptr,  g_ah);
    int*    g_degi_ptr; cudaGetSymbolAddress((void**)&g_degi_ptr, g_degi);

    const int SMS = 148;
    dim3 blk(256);

    const int GEMM_SMEM = (64 * 64 + ROWS_PER_BLK * A_STRIDE4 * 4) * 4; // 51200 B
    static bool attr_done = false;
    if (!attr_done) {
        cudaFuncSetAttribute(gemm64_kernel<float>,
            cudaFuncAttributeMaxDynamicSharedMemorySize, GEMM_SMEM);
        cudaFuncSetAttribute(gemm64_kernel<__half>,
            cudaFuncAttributeMaxDynamicSharedMemorySize, GEMM_SMEM);
        attr_done = true;
    }

    const int gemm_grid = (NNODES + ROWS_PER_BLK - 1) / ROWS_PER_BLK;  // 782
    const int agg_grid  = SMS * 24;

    // ---- CSR build ----
    cudaMemsetAsync(g_degi_ptr, 0, NNODES * sizeof(int));
    hist_kernel<<<SMS * 8, blk>>>(ei, E);
    scan_reduce_kernel<<<NSCANBLK, SCAN_BLK>>>();   // also computes dinv
    scan_bsum_kernel<<<1, 128>>>();
    scan_write_kernel<<<NSCANBLK, SCAN_BLK>>>();
    fill_kernel<<<SMS * 8, blk>>>(ei, E);

    // ---- layer 1 ----
    gemm64_kernel<float><<<gemm_grid, blk, GEMM_SMEM>>>(x, W1, g_hh_ptr, NNODES);
    agg_kernel<__half><<<agg_grid, blk>>>(g_hh_ptr, b1, g_ah_ptr);

    // ---- layer 2 ----
    gemm64_kernel<__half><<<gemm_grid, blk, GEMM_SMEM>>>(g_ah_ptr, W2, g_hh_ptr, NNODES);
    agg_kernel<float><<<agg_grid, blk>>>(g_hh_ptr, b2, out);
}

// round 13
// speedup vs baseline: 2.8380x; 1.2402x over previous
#include <cuda_runtime.h>
#include <cuda_fp16.h>
#include <stdint.h>

#define NNODES 100000
#define FDIM   64
#define EMAX   2000000   // reference uses E=1.6M; headroom

#define SCAN_BLK   1024
#define NSCANBLK   ((NNODES + SCAN_BLK - 1) / SCAN_BLK)   // 98

// ---------------------------------------------------------------------------
// Static device scratch (no allocation allowed anywhere)
// ---------------------------------------------------------------------------
__device__ __align__(16) __half g_hh[(size_t)NNODES * FDIM];  // 12.8 MB (h, fp16)
__device__ __align__(16) __half g_ah[(size_t)NNODES * FDIM];  // 12.8 MB (act, fp16)
__device__ float g_dinv[NNODES];
__device__ int   g_degi[NNODES];
__device__ int   g_off[NNODES + 1];
__device__ int   g_cursor[NNODES];
__device__ int   g_bsum[NSCANBLK];
__device__ int   g_bpre[NSCANBLK];
__device__ __align__(16) int2 g_csr[EMAX];  // {src, bitcast(dinv[src])} 16 MB

// ---------------------------------------------------------------------------
// histogram of in-edges (int atomics, exact). edge_index int32, [2, E].
// ---------------------------------------------------------------------------
__global__ void hist_kernel(const int* __restrict__ ei, long long E) {
    long long stride = (long long)gridDim.x * blockDim.x;
    for (long long e = (long long)blockIdx.x * blockDim.x + threadIdx.x;
         e < E; e += stride)
        atomicAdd(&g_degi[ei[E + e]], 1);
}

// ---------------------------------------------------------------------------
// Multi-block exclusive scan of g_degi -> g_off (+ cursor copy). 3 phases.
// Phase 1 also computes dinv (reads degi anyway).
// ---------------------------------------------------------------------------
__global__ __launch_bounds__(SCAN_BLK) void scan_reduce_kernel() {
    __shared__ int sh[SCAN_BLK / 32];
    int i = blockIdx.x * SCAN_BLK + threadIdx.x;
    int v = 0;
    if (i < NNODES) {
        v = g_degi[i];
        g_dinv[i] = rsqrtf((float)v + 1.0f);   // fused dinv
    }
    int r = v;
#pragma unroll
    for (int o = 16; o > 0; o >>= 1)
        r += __shfl_down_sync(0xffffffffu, r, o);
    if ((threadIdx.x & 31) == 0) sh[threadIdx.x >> 5] = r;
    __syncthreads();
    if (threadIdx.x < 32) {
        int w = (threadIdx.x < SCAN_BLK / 32) ? sh[threadIdx.x] : 0;
#pragma unroll
        for (int o = 16; o > 0; o >>= 1)
            w += __shfl_down_sync(0xffffffffu, w, o);
        if (threadIdx.x == 0) g_bsum[blockIdx.x] = w;
    }
}

__global__ __launch_bounds__(128) void scan_bsum_kernel() {
    __shared__ int sh[128];
    int tid = threadIdx.x;
    int v = (tid < NSCANBLK) ? g_bsum[tid] : 0;
    sh[tid] = v;
    __syncthreads();
    for (int o = 1; o < 128; o <<= 1) {
        int t = (tid >= o) ? sh[tid - o] : 0;
        __syncthreads();
        sh[tid] += t;
        __syncthreads();
    }
    if (tid < NSCANBLK) g_bpre[tid] = sh[tid] - v;   // exclusive
    if (tid == 127) g_off[NNODES] = sh[127];         // total
}

__global__ __launch_bounds__(SCAN_BLK) void scan_write_kernel() {
    __shared__ int sh[SCAN_BLK];
    int tid = threadIdx.x;
    int i = blockIdx.x * SCAN_BLK + tid;
    int v = (i < NNODES) ? g_degi[i] : 0;
    sh[tid] = v;
    __syncthreads();
    for (int o = 1; o < SCAN_BLK; o <<= 1) {
        int t = (tid >= o) ? sh[tid - o] : 0;
        __syncthreads();
        sh[tid] += t;
        __syncthreads();
    }
    if (i < NNODES) {
        int off = g_bpre[blockIdx.x] + sh[tid] - v;  // exclusive
        g_off[i]    = off;
        g_cursor[i] = off;
    }
}

// ---------------------------------------------------------------------------
// CSR fill: csr[pos] = {src, dinv[src]}  (packed 8B write per edge)
// ---------------------------------------------------------------------------
__global__ void fill_kernel(const int* __restrict__ ei, long long E) {
    long long stride = (long long)gridDim.x * blockDim.x;
    for (long long e = (long long)blockIdx.x * blockDim.x + threadIdx.x;
         e < E; e += stride) {
        int s = ei[e];
        int d = ei[E + e];
        int pos = atomicAdd(&g_cursor[d], 1);
        g_csr[pos] = make_int2(s, __float_as_int(g_dinv[s]));
    }
}

// ---------------------------------------------------------------------------
// Aggregation + epilogue (fp16 gather, fp32 accumulate):
//   out[node] = relu( dinv[n]*(sum_e dinv[s] h[s] + dinv[n] h[n]) + b )
// One warp per node; 4 quarters x 8 lanes, LDG.128 per edge row.
// ---------------------------------------------------------------------------
template <typename OutT>
__global__ __launch_bounds__(256) void agg_kernel(
    const __half* __restrict__ h, const float* __restrict__ bias,
    OutT* __restrict__ outv)
{
    const int lane = threadIdx.x & 31;
    const int eq   = lane >> 3;     // edge slot within quad: 0..3
    const int fl   = lane & 7;      // feature octet: halves [fl*8, fl*8+8)
    const int gwarp = (blockIdx.x * blockDim.x + threadIdx.x) >> 5;
    const int nwarp = (gridDim.x * blockDim.x) >> 5;

    const float4 b0 = reinterpret_cast<const float4*>(bias)[fl * 2];
    const float4 b1 = reinterpret_cast<const float4*>(bias)[fl * 2 + 1];

    for (int node = gwarp; node < NNODES; node += nwarp) {
        const int beg = g_off[node];
        const int end = g_off[node + 1];
        const float di = g_dinv[node];

        float acc[8];
        if (eq == 0) {   // self-loop handled by quarter 0
            uint4 sv = *reinterpret_cast<const uint4*>(
                h + (size_t)node * FDIM + fl * 8);
            const __half2* hp = reinterpret_cast<const __half2*>(&sv);
#pragma unroll
            for (int p = 0; p < 4; p++) {
                float2 f = __half22float2(hp[p]);
                acc[2 * p]     = di * f.x;
                acc[2 * p + 1] = di * f.y;
            }
        } else {
#pragma unroll
            for (int p = 0; p < 8; p++) acc[p] = 0.f;
        }

        int base = beg;
        for (; base + 8 <= end; base += 8) {
            int2 e0 = g_csr[base + eq];
            int2 e1 = g_csr[base + 4 + eq];
            uint4 v0 = *reinterpret_cast<const uint4*>(
                h + (size_t)e0.x * FDIM + fl * 8);
            uint4 v1 = *reinterpret_cast<const uint4*>(
                h + (size_t)e1.x * FDIM + fl * 8);
            float w0 = __int_as_float(e0.y);
            float w1 = __int_as_float(e1.y);
            const __half2* p0 = reinterpret_cast<const __half2*>(&v0);
            const __half2* p1 = reinterpret_cast<const __half2*>(&v1);
#pragma unroll
            for (int p = 0; p < 4; p++) {
                float2 f0 = __half22float2(p0[p]);
                float2 f1 = __half22float2(p1[p]);
                acc[2 * p]     = fmaf(w0, f0.x, acc[2 * p]);
                acc[2 * p + 1] = fmaf(w0, f0.y, acc[2 * p + 1]);
                acc[2 * p]     = fmaf(w1, f1.x, acc[2 * p]);
                acc[2 * p + 1] = fmaf(w1, f1.y, acc[2 * p + 1]);
            }
        }
        for (; base < end; base += 4) {
            int idx = base + eq;
            int2 e0 = g_csr[idx < end ? idx : (end - 1)];
            float w0 = (idx < end) ? __int_as_float(e0.y) : 0.f;
            uint4 v0 = *reinterpret_cast<const uint4*>(
                h + (size_t)e0.x * FDIM + fl * 8);
            const __half2* p0 = reinterpret_cast<const __half2*>(&v0);
#pragma unroll
            for (int p = 0; p < 4; p++) {
                float2 f0 = __half22float2(p0[p]);
                acc[2 * p]     = fmaf(w0, f0.x, acc[2 * p]);
                acc[2 * p + 1] = fmaf(w0, f0.y, acc[2 * p + 1]);
            }
        }

#pragma unroll
        for (int p = 0; p < 8; p++) {
            acc[p] += __shfl_xor_sync(0xffffffffu, acc[p], 8);
            acc[p] += __shfl_xor_sync(0xffffffffu, acc[p], 16);
        }

        if (eq == 0) {   // lanes 0..7 write the 64-float row
            float r[8];
            r[0] = fmaxf(fmaf(acc[0], di, b0.x), 0.f);
            r[1] = fmaxf(fmaf(acc[1], di, b0.y), 0.f);
            r[2] = fmaxf(fmaf(acc[2], di, b0.z), 0.f);
            r[3] = fmaxf(fmaf(acc[3], di, b0.w), 0.f);
            r[4] = fmaxf(fmaf(acc[4], di, b1.x), 0.f);
            r[5] = fmaxf(fmaf(acc[5], di, b1.y), 0.f);
            r[6] = fmaxf(fmaf(acc[6], di, b1.z), 0.f);
            r[7] = fmaxf(fmaf(acc[7], di, b1.w), 0.f);
            if constexpr (sizeof(OutT) == 2) {   // fp16 activations
                union { __half2 hx[4]; uint4 u; } pk;
                pk.hx[0] = __floats2half2_rn(r[0], r[1]);
                pk.hx[1] = __floats2half2_rn(r[2], r[3]);
                pk.hx[2] = __floats2half2_rn(r[4], r[5]);
                pk.hx[3] = __floats2half2_rn(r[6], r[7]);
                *reinterpret_cast<uint4*>(
                    (__half*)outv + (size_t)node * FDIM + fl * 8) = pk.u;
            } else {                             // fp32 final output
                float4* o = reinterpret_cast<float4*>(
                    (float*)outv + (size_t)node * FDIM + fl * 8);
                o[0] = make_float4(r[0], r[1], r[2], r[3]);
                o[1] = make_float4(r[4], r[5], r[6], r[7]);
            }
        }
    }
}

// ---------------------------------------------------------------------------
// Tensor-core GEMM: C[n,64] = A[n,64] @ W[64,64]
// fp16 inputs (A converted on stage), fp32 accumulate, fp16 output.
// 256 threads / 256 rows per block; warp = 32 rows (2 m16 tiles).
// A fragments hoisted (reused across all 8 n-tiles); WT smem stride 72
// makes B-fragment pairs contiguous half2 and all LDS conflict-free.
// ---------------------------------------------------------------------------
#define GROWS 256

template <typename InT>
__global__ __launch_bounds__(256) void gemm_mma_kernel(
    const InT* __restrict__ A, const float* __restrict__ W,
    __half* __restrict__ C, int n_rows)
{
    __shared__ __half sA[GROWS * 72];    // 36864 B
    __shared__ __half sWT[64 * 72];      // 9216 B (WT[n][k] = W[k][n])

    const int tid  = threadIdx.x;
    const int row0 = blockIdx.x * GROWS;

    // stage WT (fp16, transposed)
    for (int idx = tid; idx < 4096; idx += 256) {
        int k = idx >> 6, n = idx & 63;
        sWT[n * 72 + k] = __float2half_rn(W[idx]);
    }

    // stage A (fp16): 256 rows x 32 half2
    for (int i = tid; i < GROWS * 32; i += 256) {
        int r   = i >> 5;
        int c2  = i & 31;
        int row = row0 + r;
        __half2 hv = __floats2half2_rn(0.f, 0.f);
        if (row < n_rows) {
            if constexpr (sizeof(InT) == 2) {
                hv = *reinterpret_cast<const __half2*>(
                    reinterpret_cast<const __half*>(A)
                    + (size_t)row * FDIM + c2 * 2);
            } else {
                float2 f = *reinterpret_cast<const float2*>(
                    reinterpret_cast<const float*>(A)
                    + (size_t)row * FDIM + c2 * 2);
                hv = __floats2half2_rn(f.x, f.y);
            }
        }
        *reinterpret_cast<__half2*>(&sA[r * 72 + c2 * 2]) = hv;
    }
    __syncthreads();

    const int lane = tid & 31;
    const int warp = tid >> 5;
    const int r    = lane >> 2;     // 0..7 (row-in-tile / n index)
    const int cq   = lane & 3;      // 0..3 (k-pair index)
    const int wrow = warp * 32;

    // A fragments: 2 m-tiles x 4 k-chunks x 4 b32
    uint32_t afr[2][4][4];
#pragma unroll
    for (int mt = 0; mt < 2; mt++) {
        int rm = wrow + mt * 16;
#pragma unroll
        for (int kc = 0; kc < 4; kc++) {
            int kb = kc * 16;
            afr[mt][kc][0] = *reinterpret_cast<const uint32_t*>(
                &sA[(rm + r) * 72 + kb + cq * 2]);
            afr[mt][kc][1] = *reinterpret_cast<const uint32_t*>(
                &sA[(rm + r + 8) * 72 + kb + cq * 2]);
            afr[mt][kc][2] = *reinterpret_cast<const uint32_t*>(
                &sA[(rm + r) * 72 + kb + cq * 2 + 8]);
            afr[mt][kc][3] = *reinterpret_cast<const uint32_t*>(
                &sA[(rm + r + 8) * 72 + kb + cq * 2 + 8]);
        }
    }

#pragma unroll
    for (int nt = 0; nt < 8; nt++) {
        int nb = nt * 8;
        float acc[2][4] = {{0.f, 0.f, 0.f, 0.f}, {0.f, 0.f, 0.f, 0.f}};
#pragma unroll
        for (int kc = 0; kc < 4; kc++) {
            int kb = kc * 16;
            uint32_t b0 = *reinterpret_cast<const uint32_t*>(
                &sWT[(nb + r) * 72 + kb + cq * 2]);
            uint32_t b1 = *reinterpret_cast<const uint32_t*>(
                &sWT[(nb + r) * 72 + kb + cq * 2 + 8]);
#pragma unroll
            for (int mt = 0; mt < 2; mt++) {
                asm volatile(
                    "mma.sync.aligned.m16n8k16.row.col.f32.f16.f16.f32 "
                    "{%0,%1,%2,%3}, {%4,%5,%6,%7}, {%8,%9}, {%0,%1,%2,%3};"
                    : "+f"(acc[mt][0]), "+f"(acc[mt][1]),
                      "+f"(acc[mt][2]), "+f"(acc[mt][3])
                    : "r"(afr[mt][kc][0]), "r"(afr[mt][kc][1]),
                      "r"(afr[mt][kc][2]), "r"(afr[mt][kc][3]),
                      "r"(b0), "r"(b1));
            }
        }
#pragma unroll
        for (int mt = 0; mt < 2; mt++) {
            int row = row0 + wrow + mt * 16 + r;
            int col = nb + cq * 2;
            if (row < n_rows)
                *reinterpret_cast<__half2*>(C + (size_t)row * FDIM + col) =
                    __floats2half2_rn(acc[mt][0], acc[mt][1]);
            if (row + 8 < n_rows)
                *reinterpret_cast<__half2*>(C + (size_t)(row + 8) * FDIM + col) =
                    __floats2half2_rn(acc[mt][2], acc[mt][3]);
        }
    }
}

// ---------------------------------------------------------------------------
extern "C" void kernel_launch(void* const* d_in, const int* in_sizes, int n_in,
                              void* d_out, int out_size)
{
    const float* x  = (const float*)d_in[0];
    const int*   ei = (const int*)d_in[1];     // int32 (JAX x64 disabled)
    const float* W1 = (const float*)d_in[2];
    const float* b1 = (const float*)d_in[3];
    const float* W2 = (const float*)d_in[4];
    const float* b2 = (const float*)d_in[5];
    float* out = (float*)d_out;

    const long long E = (long long)in_sizes[1] / 2;

    __half* g_hh_ptr;  cudaGetSymbolAddress((void**)&g_hh_ptr,  g_hh);
    __half* g_ah_ptr;  cudaGetSymbolAddress((void**)&g_ah_ptr,  g_ah);
    int*    g_degi_ptr; cudaGetSymbolAddress((void**)&g_degi_ptr, g_degi);

    const int SMS = 148;
    dim3 blk(256);

    const int gemm_grid = (NNODES + GROWS - 1) / GROWS;   // 391
    const int agg_grid  = SMS * 24;

    // ---- CSR build ----
    cudaMemsetAsync(g_degi_ptr, 0, NNODES * sizeof(int));
    hist_kernel<<<SMS * 8, blk>>>(ei, E);
    scan_reduce_kernel<<<NSCANBLK, SCAN_BLK>>>();   // also computes dinv
    scan_bsum_kernel<<<1, 128>>>();
    scan_write_kernel<<<NSCANBLK, SCAN_BLK>>>();
    fill_kernel<<<SMS * 8, blk>>>(ei, E);

    // ---- layer 1 ----
    gemm_mma_kernel<float><<<gemm_grid, blk>>>(x, W1, g_hh_ptr, NNODES);
    agg_kernel<__half><<<agg_grid, blk>>>(g_hh_ptr, b1, g_ah_ptr);

    // ---- layer 2 ----
    gemm_mma_kernel<__half><<<gemm_grid, blk>>>(g_ah_ptr, W2, g_hh_ptr, NNODES);
    agg_kernel<float><<<agg_grid, blk>>>(g_hh_ptr, b2, out);
}